// round 7
// baseline (speedup 1.0000x reference)
#include <cuda_runtime.h>
#include <cuda_bf16.h>
#include <math.h>
#include <stdint.h>

#define BATCH   16384
#define HID     1024
#define CTXK    512
#define N4      4096
#define TSTEPS  60
#define INW     516     // W_ih row width (C+4)

// gates GEMM: A row = [h_hi(1024) | h_lo(1024) | eblk(64)] -> AGLD=2112
// K layout    = [h_hi | h_lo | h_hi(re-read) | eblk]  -> KG=3136 = 49*64
#define AGLD    2112
#define EBLK    2048       // e-block offset in A row
#define KG      3136
// ffn GEMM: A row = [y_hi(1024) | y_lo(1024)]; K = [y_hi|y_lo|y_hi] = 3072
#define AFLD    2048
#define KF      3072
// context GEMMs: A row = [c_hi(512) | c_lo(512)]; K = [hi|lo|hi] = 1536
#define ACLD    1024
#define KC      1536

// ------------------------- scratch (device globals) -------------------------
__device__ __align__(256) float          g_gctx[(size_t)BATCH * N4];
__device__ __align__(256) __nv_bfloat16  g_Ag0[(size_t)BATCH * AGLD];
__device__ __align__(256) __nv_bfloat16  g_Ag1[(size_t)BATCH * AGLD];
__device__ __align__(256) __nv_bfloat16  g_Af [(size_t)BATCH * AFLD];
__device__ __align__(256) __nv_bfloat16  g_ctxs[(size_t)BATCH * ACLD];
__device__ __align__(256) float          g_c  [(size_t)BATCH * HID];
__device__ __align__(256) float          g_y2 [(size_t)BATCH * HID];
__device__ __align__(256) float          g_pos[(size_t)BATCH * 2];
__device__ __align__(256) __nv_bfloat16  g_Wg  [(size_t)N4 * KG];
__device__ __align__(256) __nv_bfloat16  g_Wc4 [(size_t)N4 * KC];
__device__ __align__(256) __nv_bfloat16  g_Whh [(size_t)HID * KC];
__device__ __align__(256) __nv_bfloat16  g_Wcc [(size_t)HID * KC];
__device__ __align__(256) __nv_bfloat16  g_W1s [(size_t)HID * KF];
__device__ __align__(256) float          g_bsum[N4];

// ------------------------- low-level helpers -------------------------
#define SW128(b) ((b) ^ (((b) >> 3) & 0x70))

__device__ __forceinline__ void cpasync16(uint32_t dst, const void* src) {
    asm volatile("cp.async.cg.shared.global [%0],[%1],16;\n" :: "r"(dst), "l"(src));
}
__device__ __forceinline__ void ldsm4(uint32_t* r, uint32_t addr) {
    asm volatile("ldmatrix.sync.aligned.m8n8.x4.shared.b16 {%0,%1,%2,%3}, [%4];"
                 : "=r"(r[0]), "=r"(r[1]), "=r"(r[2]), "=r"(r[3]) : "r"(addr));
}
__device__ __forceinline__ void mma16816(float* c, const uint32_t* a, const uint32_t* b) {
    asm volatile(
        "mma.sync.aligned.m16n8k16.row.col.f32.bf16.bf16.f32 "
        "{%0,%1,%2,%3},{%4,%5,%6,%7},{%8,%9},{%0,%1,%2,%3};\n"
        : "+f"(c[0]), "+f"(c[1]), "+f"(c[2]), "+f"(c[3])
        : "r"(a[0]), "r"(a[1]), "r"(a[2]), "r"(a[3]), "r"(b[0]), "r"(b[1]));
}
__device__ __forceinline__ __nv_bfloat16 bhi(float v) { return __float2bfloat16(v); }
__device__ __forceinline__ __nv_bfloat16 blo(float v) {
    return __float2bfloat16(v - __bfloat162float(__float2bfloat16(v)));
}

// ------------------------- prep (2 kernels for ncu launch alignment) -------------------------
__global__ void prep_weights(const float* __restrict__ Whh, const float* __restrict__ Wih,
                             const float* __restrict__ b_ih, const float* __restrict__ b_hh,
                             const float* __restrict__ Wh, const float* __restrict__ Wc,
                             const float* __restrict__ W1) {
    const long n_wg = (long)N4 * KG;          // 12,845,056
    const long n_wc = (long)N4 * KC;          // 6,291,456
    const long n_s  = (long)HID * CTXK;       // 524,288
    const long n_w1 = (long)HID * HID;        // 1,048,576
    long i = (long)blockIdx.x * blockDim.x + threadIdx.x;

    if (i < n_wg) {
        int np = (int)(i / KG), k = (int)(i % KG);
        int r = (np & 3) * HID + (np >> 2);
        float w = 0.f; int lo = 0;
        if (k < 1024)        { w = Whh[(size_t)r * HID + k]; }
        else if (k < 2048)   { w = Whh[(size_t)r * HID + (k - 1024)]; }
        else if (k < 3072)   { w = Whh[(size_t)r * HID + (k - 2048)]; lo = 1; }
        else {
            int q = k - 3072;
            if (q < 4)        w = Wih[(size_t)r * INW + CTXK + q];
            else if (q < 8)   w = Wih[(size_t)r * INW + CTXK + (q - 4)];
            else if (q < 12) { w = Wih[(size_t)r * INW + CTXK + (q - 8)]; lo = 1; }
        }
        g_Wg[(size_t)np * KG + k] = lo ? blo(w) : bhi(w);
        return;
    }
    i -= n_wg;
    if (i < n_wc) {   // W_ih ctx part: rows n'=4j+g, layout [hi(512)|hi(512)|lo(512)]
        int np = (int)(i / KC), k = (int)(i % KC);
        int r = (np & 3) * HID + (np >> 2);
        int src = (k < 512) ? k : (k < 1024 ? k - 512 : k - 1024);
        float w = Wih[(size_t)r * INW + src];
        g_Wc4[(size_t)np * KC + k] = (k < 1024) ? bhi(w) : blo(w);
        return;
    }
    i -= n_wc;
    if (i < N4) {
        int r = ((int)i & 3) * HID + ((int)i >> 2);
        g_bsum[i] = b_ih[r] + b_hh[r];
        return;
    }
    i -= N4;
    if (i < n_s) {    // Wh split [hi|hi|lo] width 512
        int r = (int)(i / CTXK), k = (int)(i % CTXK);
        float w = Wh[(size_t)r * CTXK + k];
        size_t b = (size_t)r * KC;
        g_Whh[b + k] = bhi(w); g_Whh[b + 512 + k] = bhi(w); g_Whh[b + 1024 + k] = blo(w);
        return;
    }
    i -= n_s;
    if (i < n_s) {
        int r = (int)(i / CTXK), k = (int)(i % CTXK);
        float w = Wc[(size_t)r * CTXK + k];
        size_t b = (size_t)r * KC;
        g_Wcc[b + k] = bhi(w); g_Wcc[b + 512 + k] = bhi(w); g_Wcc[b + 1024 + k] = blo(w);
        return;
    }
    i -= n_s;
    if (i < n_w1) {   // W1 split [hi|hi|lo] width 1024
        int r = (int)(i / HID), k = (int)(i % HID);
        float w = W1[(size_t)r * HID + k];
        size_t b = (size_t)r * KF;
        g_W1s[b + k] = bhi(w); g_W1s[b + 1024 + k] = bhi(w); g_W1s[b + 2048 + k] = blo(w);
    }
}

__global__ void prep_data(const float* __restrict__ ctx,
                          const float* __restrict__ last_pos,
                          const float* __restrict__ last_delta) {
    const long n_cs = (long)BATCH * CTXK;
    long i = (long)blockIdx.x * blockDim.x + threadIdx.x;
    if (i < n_cs) {
        int b = (int)(i / CTXK), k = (int)(i % CTXK);
        float v = ctx[i];
        g_ctxs[(size_t)b * ACLD + k]       = bhi(v);
        g_ctxs[(size_t)b * ACLD + 512 + k] = blo(v);
        return;
    }
    i -= n_cs;
    if (i < BATCH) {
        int b = (int)i;
        g_pos[b * 2 + 0] = last_pos[b * 2 + 0];
        g_pos[b * 2 + 1] = last_pos[b * 2 + 1];
        float d0 = last_delta[b * 2 + 0], d1 = last_delta[b * 2 + 1];
        float nn = fmaxf(sqrtf(d0 * d0 + d1 * d1), 1e-6f);
        float e[4] = {d0, d1, d0 / nn, d1 / nn};
        size_t base = (size_t)b * AGLD;
#pragma unroll
        for (int q = 0; q < 4; q++) {
            g_Ag0[base + EBLK + q]      = bhi(e[q]);
            g_Ag0[base + EBLK + 4 + q]  = blo(e[q]);
            g_Ag0[base + EBLK + 8 + q]  = bhi(e[q]);
        }
        __nv_bfloat16 z = __float2bfloat16(0.f);
        for (int k = EBLK + 12; k < AGLD; k++) { g_Ag0[base + k] = z; g_Ag1[base + k] = z; }
    }
}

// ------------------------- GEMM engine v3 -------------------------
// CTA tile 128(M)x256(N), 8 warps (2M x 4N), warp tile 64x64, KTILE=64,
// 3-slot smem ring / 2 tiles in flight, one __syncthreads per K-tile.
#define TK 64
#define NSTG 3
#define STG_BYTES 49152          // A 16KB + B 32KB
#define GEMM_SMEM (NSTG * STG_BYTES)
#define CTAN 256

enum { EPI_CTX = 0, EPI_TANH_SPLIT = 1, EPI_TANH_C = 2, EPI_GATES = 3, EPI_GELU = 4 };

__device__ __forceinline__ void lstm_cell(float* cbuf, __nv_bfloat16* outs, int row, int j,
                                          float gi, float gf, float gg, float go) {
    float cold = cbuf[(size_t)row * HID + j];
    float si = 1.f / (1.f + expf(-gi));
    float sf = 1.f / (1.f + expf(-gf));
    float so = 1.f / (1.f + expf(-go));
    float tg = tanhf(gg);
    float cn = sf * cold + si * tg;
    float h  = so * tanhf(cn);
    cbuf[(size_t)row * HID + j] = cn;
    outs[(size_t)row * AGLD + j]        = bhi(h);
    outs[(size_t)row * AGLD + 1024 + j] = blo(h);
}

template <int EPI>
__global__ void __launch_bounds__(256)
gemm3(const __nv_bfloat16* __restrict__ A, int lda,
      const __nv_bfloat16* __restrict__ W, int ktot,
      int s1, int d1, int s2, int d2,        // K->A col mapping
      const float* __restrict__ aux,
      float* __restrict__ outf,
      __nv_bfloat16* __restrict__ outs,
      int nOut) {
    extern __shared__ __align__(1024) char smp[];
    const uint32_t sbase = (uint32_t)__cvta_generic_to_shared(smp);

    const int tid = threadIdx.x;
    const int lane = tid & 31, wid = tid >> 5;
    const int wm = wid >> 2, wn = wid & 3;          // 2M x 4N
    const int m0 = blockIdx.y * 128, n0 = blockIdx.x * CTAN;
    const int nK = ktot / TK;

    float acc[4][8][4];
#pragma unroll
    for (int a = 0; a < 4; a++)
#pragma unroll
        for (int b = 0; b < 8; b++)
#pragma unroll
            for (int c = 0; c < 4; c++) acc[a][b][c] = 0.f;

    auto fill = [&](int kt) {
        int slot = kt % NSTG;
        uint32_t sA = sbase + slot * STG_BYTES;
        uint32_t sB = sA + 16384;
        int k0 = kt * TK;
        int cb = (k0 < s1) ? k0 : ((k0 < s2) ? k0 - d1 : k0 - d2);
#pragma unroll
        for (int t = 0; t < 4; t++) {              // A: 128 rows x 64 cols
            int c = tid + t * 256;
            int row = c >> 3, ch = c & 7;
            cpasync16(sA + SW128(row * 128 + ch * 16),
                      A + (size_t)(m0 + row) * lda + cb + ch * 8);
        }
#pragma unroll
        for (int t = 0; t < 8; t++) {              // B: 256 rows x 64 cols
            int c = tid + t * 256;
            int row = c >> 3, ch = c & 7;
            cpasync16(sB + SW128(row * 128 + ch * 16),
                      W + (size_t)(n0 + row) * ktot + k0 + ch * 8);
        }
        asm volatile("cp.async.commit_group;\n");
    };

    fill(0);
    if (nK > 1) fill(1);

    const int g  = lane >> 3;
    const int lr = lane & 7;

    for (int kt = 0; kt < nK; kt++) {
        if (kt + 1 < nK) asm volatile("cp.async.wait_group 1;\n");
        else             asm volatile("cp.async.wait_group 0;\n");
        __syncthreads();
        if (kt + 2 < nK) fill(kt + 2);     // overwrites slot (kt-1)%3: all readers done

        int slot = kt % NSTG;
        uint32_t sA = sbase + slot * STG_BYTES;
        uint32_t sB = sA + 16384;

#pragma unroll
        for (int ks = 0; ks < 4; ks++) {
            uint32_t a[4][4], b[4][4];
#pragma unroll
            for (int mf = 0; mf < 4; mf++) {
                int row = wm * 64 + mf * 16 + lr + ((g & 1) << 3);
                ldsm4(a[mf], sA + SW128(row * 128 + ks * 32 + ((g >> 1) << 4)));
            }
#pragma unroll
            for (int nf = 0; nf < 4; nf++) {
                int row = wn * 64 + nf * 16 + lr + ((g >> 1) << 3);
                ldsm4(b[nf], sB + SW128(row * 128 + ks * 32 + ((g & 1) << 4)));
            }
#pragma unroll
            for (int mf = 0; mf < 4; mf++) {
#pragma unroll
                for (int nf = 0; nf < 4; nf++) {
                    mma16816(acc[mf][2 * nf],     a[mf], &b[nf][0]);
                    mma16816(acc[mf][2 * nf + 1], a[mf], &b[nf][2]);
                }
            }
        }
    }

    // ------------------------- epilogue -------------------------
#pragma unroll
    for (int mt = 0; mt < 4; mt++) {
#pragma unroll
        for (int nt = 0; nt < 8; nt++) {
            int r = m0 + wm * 64 + mt * 16 + (lane >> 2);
            int n = n0 + wn * 64 + nt * 8 + (lane & 3) * 2;
            float v0 = acc[mt][nt][0], v1 = acc[mt][nt][1];
            float v2 = acc[mt][nt][2], v3 = acc[mt][nt][3];

            if (EPI == EPI_CTX) {
                outf[(size_t)r * nOut + n]           = v0 + aux[n];
                outf[(size_t)r * nOut + n + 1]       = v1 + aux[n + 1];
                outf[(size_t)(r + 8) * nOut + n]     = v2 + aux[n];
                outf[(size_t)(r + 8) * nOut + n + 1] = v3 + aux[n + 1];
            } else if (EPI == EPI_TANH_C) {
                outf[(size_t)r * nOut + n]           = tanhf(v0 + aux[n]);
                outf[(size_t)r * nOut + n + 1]       = tanhf(v1 + aux[n + 1]);
                outf[(size_t)(r + 8) * nOut + n]     = tanhf(v2 + aux[n]);
                outf[(size_t)(r + 8) * nOut + n + 1] = tanhf(v3 + aux[n + 1]);
            } else if (EPI == EPI_TANH_SPLIT) {
#pragma unroll
                for (int q = 0; q < 4; q++) {
                    int rr = (q >= 2) ? r + 8 : r;
                    int nn = n + (q & 1);
                    float v = (q == 0) ? v0 : (q == 1) ? v1 : (q == 2) ? v2 : v3;
                    float h = tanhf(v + aux[nn]);
                    outs[(size_t)rr * AGLD + nn]        = bhi(h);
                    outs[(size_t)rr * AGLD + 1024 + nn] = blo(h);
                }
            } else if (EPI == EPI_GELU) {
#pragma unroll
                for (int q = 0; q < 4; q++) {
                    int rr = (q >= 2) ? r + 8 : r;
                    int nn = n + (q & 1);
                    float v = (q == 0) ? v0 : (q == 1) ? v1 : (q == 2) ? v2 : v3;
                    float u = v + aux[nn];
                    outf[(size_t)rr * nOut + nn] = 0.5f * u * (1.f + erff(u * 0.70710678118654752f));
                }
            } else { // EPI_GATES
                float w0 = v0 + aux[(size_t)r * N4 + n];
                float w1 = v1 + aux[(size_t)r * N4 + n + 1];
                float w2 = v2 + aux[(size_t)(r + 8) * N4 + n];
                float w3 = v3 + aux[(size_t)(r + 8) * N4 + n + 1];
                float u0 = __shfl_xor_sync(0xffffffffu, w0, 1);
                float u1 = __shfl_xor_sync(0xffffffffu, w1, 1);
                float u2 = __shfl_xor_sync(0xffffffffu, w2, 1);
                float u3 = __shfl_xor_sync(0xffffffffu, w3, 1);
                if (!(lane & 1)) {   // even lanes own (i,f); lane^1 holds (g,o)
                    int j = n >> 2;
                    lstm_cell(outf, outs, r, j, w0, w1, u0, u1);
                    lstm_cell(outf, outs, r + 8, j, w2, w3, u2, u3);
                }
            }
        }
    }
}

// ------------------------- LayerNorm (warp per row) -------------------------
__global__ void ln_kernel(const __nv_bfloat16* __restrict__ Ag,
                          const float* __restrict__ gam, const float* __restrict__ bet) {
    int warp = (blockIdx.x * blockDim.x + threadIdx.x) >> 5;
    int lane = threadIdx.x & 31;
    if (warp >= BATCH) return;
    size_t base = (size_t)warp * AGLD;
    float h[32];
    float s = 0.f, ss = 0.f;
#pragma unroll
    for (int i = 0; i < 32; i++) {
        int k = lane + 32 * i;
        float v = __bfloat162float(Ag[base + k]) + __bfloat162float(Ag[base + 1024 + k]);
        h[i] = v; s += v; ss += v * v;
    }
#pragma unroll
    for (int o = 16; o; o >>= 1) {
        s  += __shfl_xor_sync(0xffffffffu, s, o);
        ss += __shfl_xor_sync(0xffffffffu, ss, o);
    }
    float mu = s * (1.f / HID);
    float var = ss * (1.f / HID) - mu * mu;
    float inv = rsqrtf(var + 1e-5f);
    size_t ob = (size_t)warp * AFLD;
#pragma unroll
    for (int i = 0; i < 32; i++) {
        int k = lane + 32 * i;
        float y = (h[i] - mu) * inv * gam[k] + bet[k];
        g_Af[ob + k]        = bhi(y);
        g_Af[ob + 1024 + k] = blo(y);
    }
}

// ------------------------- delta / pos head (warp per row) -------------------------
__global__ void delta_kernel(const float* __restrict__ W2, const float* __restrict__ b2,
                             float* __restrict__ out, int t, __nv_bfloat16* __restrict__ AgN) {
    int warp = (blockIdx.x * blockDim.x + threadIdx.x) >> 5;
    int lane = threadIdx.x & 31;
    if (warp >= BATCH) return;
    const float* y = g_y2 + (size_t)warp * HID;
    float a0 = 0.f, a1 = 0.f;
#pragma unroll
    for (int i = 0; i < 32; i++) {
        int k = lane + 32 * i;
        float v = y[k];
        a0 += v * W2[k];
        a1 += v * W2[HID + k];
    }
#pragma unroll
    for (int o = 16; o; o >>= 1) {
        a0 += __shfl_xor_sync(0xffffffffu, a0, o);
        a1 += __shfl_xor_sync(0xffffffffu, a1, o);
    }
    if (lane == 0) {
        float d0 = a0 + b2[0], d1 = a1 + b2[1];
        float p0 = g_pos[warp * 2 + 0] + d0;
        float p1 = g_pos[warp * 2 + 1] + d1;
        g_pos[warp * 2 + 0] = p0;
        g_pos[warp * 2 + 1] = p1;
        out[(size_t)warp * (TSTEPS * 2) + t * 2 + 0] = p0;
        out[(size_t)warp * (TSTEPS * 2) + t * 2 + 1] = p1;
        float nn = fmaxf(sqrtf(d0 * d0 + d1 * d1), 1e-6f);
        float e[4] = {d0, d1, d0 / nn, d1 / nn};
        size_t base = (size_t)warp * AGLD;
#pragma unroll
        for (int q = 0; q < 4; q++) {
            AgN[base + EBLK + q]     = bhi(e[q]);
            AgN[base + EBLK + 4 + q] = blo(e[q]);
            AgN[base + EBLK + 8 + q] = bhi(e[q]);
        }
    }
}

// ------------------------- host -------------------------
static inline int nb(long n) { return (int)((n + 255) / 256); }

extern "C" void kernel_launch(void* const* d_in, const int* in_sizes, int n_in,
                              void* d_out, int out_size) {
    const float* context    = (const float*)d_in[0];
    const float* last_pos   = (const float*)d_in[1];
    const float* last_delta = (const float*)d_in[2];
    const float* Wh   = (const float*)d_in[3];
    const float* bh   = (const float*)d_in[4];
    const float* Wc   = (const float*)d_in[5];
    const float* bc   = (const float*)d_in[6];
    const float* W_ih = (const float*)d_in[7];
    const float* b_ih = (const float*)d_in[8];
    const float* W_hh = (const float*)d_in[9];
    const float* b_hh = (const float*)d_in[10];
    const float* ln_g = (const float*)d_in[11];
    const float* ln_b = (const float*)d_in[12];
    const float* W1   = (const float*)d_in[13];
    const float* b1   = (const float*)d_in[14];
    const float* W2   = (const float*)d_in[15];
    const float* b2   = (const float*)d_in[16];
    float* out = (float*)d_out;

    __nv_bfloat16 *pCtxs, *pAg0, *pAg1, *pAf, *pWg, *pWc4, *pWhh, *pWcc, *pW1s;
    float *pGctx, *pC, *pY2, *pBsum;
    cudaGetSymbolAddress((void**)&pCtxs, g_ctxs);
    cudaGetSymbolAddress((void**)&pAg0, g_Ag0);
    cudaGetSymbolAddress((void**)&pAg1, g_Ag1);
    cudaGetSymbolAddress((void**)&pAf,  g_Af);
    cudaGetSymbolAddress((void**)&pWg,  g_Wg);
    cudaGetSymbolAddress((void**)&pWc4, g_Wc4);
    cudaGetSymbolAddress((void**)&pWhh, g_Whh);
    cudaGetSymbolAddress((void**)&pWcc, g_Wcc);
    cudaGetSymbolAddress((void**)&pW1s, g_W1s);
    cudaGetSymbolAddress((void**)&pGctx, g_gctx);
    cudaGetSymbolAddress((void**)&pC,   g_c);
    cudaGetSymbolAddress((void**)&pY2,  g_y2);
    cudaGetSymbolAddress((void**)&pBsum, g_bsum);

    cudaFuncSetAttribute(gemm3<EPI_CTX>,        cudaFuncAttributeMaxDynamicSharedMemorySize, GEMM_SMEM);
    cudaFuncSetAttribute(gemm3<EPI_TANH_SPLIT>, cudaFuncAttributeMaxDynamicSharedMemorySize, GEMM_SMEM);
    cudaFuncSetAttribute(gemm3<EPI_TANH_C>,     cudaFuncAttributeMaxDynamicSharedMemorySize, GEMM_SMEM);
    cudaFuncSetAttribute(gemm3<EPI_GATES>,      cudaFuncAttributeMaxDynamicSharedMemorySize, GEMM_SMEM);
    cudaFuncSetAttribute(gemm3<EPI_GELU>,       cudaFuncAttributeMaxDynamicSharedMemorySize, GEMM_SMEM);

    const int BIG = 1 << 30;

    // launch #0, #1: prep (merged so launch #5 = first gates GEMM for ncu -s 5)
    {
        long tot = (long)N4 * KG + (long)N4 * KC + N4
                 + (long)HID * CTXK * 2 + (long)HID * HID;
        prep_weights<<<nb(tot), 256>>>(W_hh, W_ih, b_ih, b_hh, Wh, Wc, W1);
    }
    {
        long tot = (long)BATCH * CTXK + BATCH;
        prep_data<<<nb(tot), 256>>>(context, last_pos, last_delta);
    }

    dim3 blk(256);
    dim3 grid_n4(N4 / CTAN, BATCH / 128);   // (16,128)
    dim3 grid_h(HID / CTAN, BATCH / 128);   // (4,128)

    // #2 gates_ctx ; #3 hidden init ; #4 cell init
    gemm3<EPI_CTX><<<grid_n4, blk, GEMM_SMEM>>>(pCtxs, ACLD, pWc4, KC, 1024, 1024, BIG, 0,
                                                pBsum, pGctx, nullptr, N4);
    gemm3<EPI_TANH_SPLIT><<<grid_h, blk, GEMM_SMEM>>>(pCtxs, ACLD, pWhh, KC, 1024, 1024, BIG, 0,
                                                      bh, nullptr, pAg0, HID);
    gemm3<EPI_TANH_C><<<grid_h, blk, GEMM_SMEM>>>(pCtxs, ACLD, pWcc, KC, 1024, 1024, BIG, 0,
                                                  bc, pC, nullptr, HID);

    __nv_bfloat16* Ag[2] = {pAg0, pAg1};
    for (int t = 0; t < TSTEPS; t++) {
        int cur = t & 1, nxt = cur ^ 1;
        gemm3<EPI_GATES><<<grid_n4, blk, GEMM_SMEM>>>(Ag[cur], AGLD, pWg, KG, 2048, 2048, 3072, 1024,
                                                      pGctx, pC, Ag[nxt], N4);
        ln_kernel<<<BATCH / 8, 256>>>(Ag[nxt], ln_g, ln_b);
        gemm3<EPI_GELU><<<grid_h, blk, GEMM_SMEM>>>(pAf, AFLD, pW1s, KF, 2048, 2048, BIG, 0,
                                                    b1, pY2, nullptr, HID);
        delta_kernel<<<BATCH / 8, 256>>>(W2, b2, out, t, Ag[nxt]);
    }
}

// round 8
// speedup vs baseline: 1.4346x; 1.4346x over previous
#include <cuda_runtime.h>
#include <cuda_bf16.h>
#include <math.h>
#include <stdint.h>

#define BATCH   16384
#define HID     1024
#define CTXK    512
#define N4      4096
#define TSTEPS  60
#define INW     516     // W_ih row width (C+4)

// gates GEMM: A row = [h_hi(1024) | h_lo(1024) | eblk(64)] -> AGLD=2112
// K layout    = [h_hi | h_lo | h_hi(re-read) | eblk]  -> KG=3136 = 49*64
#define AGLD    2112
#define EBLK    2048       // e-block offset in A row
#define KG      3136
// ffn GEMM: A row = [y_hi(1024) | y_lo(1024)]; K = [y_hi|y_lo|y_hi] = 3072
#define AFLD    2048
#define KF      3072
// context GEMMs: A row = [c_hi(512) | c_lo(512)]; K = [hi-part|lo-part|hi-part] = 1536
#define ACLD    1024
#define KC      1536

// ------------------------- scratch (device globals) -------------------------
__device__ __align__(256) float          g_gctx[(size_t)BATCH * N4];
__device__ __align__(256) __nv_bfloat16  g_Ag0[(size_t)BATCH * AGLD];
__device__ __align__(256) __nv_bfloat16  g_Ag1[(size_t)BATCH * AGLD];
__device__ __align__(256) __nv_bfloat16  g_Af [(size_t)BATCH * AFLD];
__device__ __align__(256) __nv_bfloat16  g_ctxs[(size_t)BATCH * ACLD];
__device__ __align__(256) float          g_c  [(size_t)BATCH * HID];
__device__ __align__(256) float          g_y2 [(size_t)BATCH * HID];
__device__ __align__(256) float          g_pos[(size_t)BATCH * 2];
__device__ __align__(256) __nv_bfloat16  g_Wg  [(size_t)N4 * KG];
__device__ __align__(256) __nv_bfloat16  g_Wc4 [(size_t)N4 * KC];
__device__ __align__(256) __nv_bfloat16  g_Whh [(size_t)HID * KC];
__device__ __align__(256) __nv_bfloat16  g_Wcc [(size_t)HID * KC];
__device__ __align__(256) __nv_bfloat16  g_W1s [(size_t)HID * KF];
__device__ __align__(256) float          g_bsum[N4];

// ------------------------- low-level helpers -------------------------
#define SW128(b) ((b) ^ (((b) >> 3) & 0x70))

__device__ __forceinline__ void cpasync16(uint32_t dst, const void* src) {
    asm volatile("cp.async.cg.shared.global [%0],[%1],16;\n" :: "r"(dst), "l"(src));
}
__device__ __forceinline__ void ldsm4(uint32_t* r, uint32_t addr) {
    asm volatile("ldmatrix.sync.aligned.m8n8.x4.shared.b16 {%0,%1,%2,%3}, [%4];"
                 : "=r"(r[0]), "=r"(r[1]), "=r"(r[2]), "=r"(r[3]) : "r"(addr));
}
__device__ __forceinline__ void mma16816(float* c, const uint32_t* a, const uint32_t* b) {
    asm volatile(
        "mma.sync.aligned.m16n8k16.row.col.f32.bf16.bf16.f32 "
        "{%0,%1,%2,%3},{%4,%5,%6,%7},{%8,%9},{%0,%1,%2,%3};\n"
        : "+f"(c[0]), "+f"(c[1]), "+f"(c[2]), "+f"(c[3])
        : "r"(a[0]), "r"(a[1]), "r"(a[2]), "r"(a[3]), "r"(b[0]), "r"(b[1]));
}
__device__ __forceinline__ __nv_bfloat16 bhi(float v) { return __float2bfloat16(v); }
__device__ __forceinline__ __nv_bfloat16 blo(float v) {
    return __float2bfloat16(v - __bfloat162float(__float2bfloat16(v)));
}

// ------------------------- prep (2 kernels for ncu launch alignment) -------------------------
__global__ void prep_weights(const float* __restrict__ Whh, const float* __restrict__ Wih,
                             const float* __restrict__ b_ih, const float* __restrict__ b_hh,
                             const float* __restrict__ Wh, const float* __restrict__ Wc,
                             const float* __restrict__ W1) {
    const long n_wg = (long)N4 * KG;
    const long n_wc = (long)N4 * KC;
    const long n_s  = (long)HID * CTXK;
    const long n_w1 = (long)HID * HID;
    long i = (long)blockIdx.x * blockDim.x + threadIdx.x;

    if (i < n_wg) {
        int np = (int)(i / KG), k = (int)(i % KG);
        int r = (np & 3) * HID + (np >> 2);
        float w = 0.f; int lo = 0;
        if (k < 1024)        { w = Whh[(size_t)r * HID + k]; }
        else if (k < 2048)   { w = Whh[(size_t)r * HID + (k - 1024)]; }
        else if (k < 3072)   { w = Whh[(size_t)r * HID + (k - 2048)]; lo = 1; }
        else {
            int q = k - 3072;
            if (q < 4)        w = Wih[(size_t)r * INW + CTXK + q];
            else if (q < 8)   w = Wih[(size_t)r * INW + CTXK + (q - 4)];
            else if (q < 12) { w = Wih[(size_t)r * INW + CTXK + (q - 8)]; lo = 1; }
        }
        g_Wg[(size_t)np * KG + k] = lo ? blo(w) : bhi(w);
        return;
    }
    i -= n_wg;
    if (i < n_wc) {   // W_ih ctx part: rows n'=4j+g, layout [hi(512)|hi(512)|lo(512)]
        int np = (int)(i / KC), k = (int)(i % KC);
        int r = (np & 3) * HID + (np >> 2);
        int src = (k < 512) ? k : (k < 1024 ? k - 512 : k - 1024);
        float w = Wih[(size_t)r * INW + src];
        g_Wc4[(size_t)np * KC + k] = (k < 1024) ? bhi(w) : blo(w);
        return;
    }
    i -= n_wc;
    if (i < N4) {
        int r = ((int)i & 3) * HID + ((int)i >> 2);
        g_bsum[i] = b_ih[r] + b_hh[r];
        return;
    }
    i -= N4;
    if (i < n_s) {    // Wh split [hi|hi|lo] width 512
        int r = (int)(i / CTXK), k = (int)(i % CTXK);
        float w = Wh[(size_t)r * CTXK + k];
        size_t b = (size_t)r * KC;
        g_Whh[b + k] = bhi(w); g_Whh[b + 512 + k] = bhi(w); g_Whh[b + 1024 + k] = blo(w);
        return;
    }
    i -= n_s;
    if (i < n_s) {
        int r = (int)(i / CTXK), k = (int)(i % CTXK);
        float w = Wc[(size_t)r * CTXK + k];
        size_t b = (size_t)r * KC;
        g_Wcc[b + k] = bhi(w); g_Wcc[b + 512 + k] = bhi(w); g_Wcc[b + 1024 + k] = blo(w);
        return;
    }
    i -= n_s;
    if (i < n_w1) {   // W1 split [hi|hi|lo] width 1024
        int r = (int)(i / HID), k = (int)(i % HID);
        float w = W1[(size_t)r * HID + k];
        size_t b = (size_t)r * KF;
        g_W1s[b + k] = bhi(w); g_W1s[b + 1024 + k] = bhi(w); g_W1s[b + 2048 + k] = blo(w);
    }
}

__global__ void prep_data(const float* __restrict__ ctx,
                          const float* __restrict__ last_pos,
                          const float* __restrict__ last_delta) {
    const long n_cs = (long)BATCH * CTXK;
    long i = (long)blockIdx.x * blockDim.x + threadIdx.x;
    if (i < n_cs) {
        int b = (int)(i / CTXK), k = (int)(i % CTXK);
        float v = ctx[i];
        g_ctxs[(size_t)b * ACLD + k]       = bhi(v);
        g_ctxs[(size_t)b * ACLD + 512 + k] = blo(v);
        return;
    }
    i -= n_cs;
    if (i < BATCH) {
        int b = (int)i;
        g_pos[b * 2 + 0] = last_pos[b * 2 + 0];
        g_pos[b * 2 + 1] = last_pos[b * 2 + 1];
        float d0 = last_delta[b * 2 + 0], d1 = last_delta[b * 2 + 1];
        float nn = fmaxf(sqrtf(d0 * d0 + d1 * d1), 1e-6f);
        float e[4] = {d0, d1, d0 / nn, d1 / nn};
        size_t base = (size_t)b * AGLD;
#pragma unroll
        for (int q = 0; q < 4; q++) {
            g_Ag0[base + EBLK + q]      = bhi(e[q]);
            g_Ag0[base + EBLK + 4 + q]  = blo(e[q]);
            g_Ag0[base + EBLK + 8 + q]  = bhi(e[q]);
        }
        __nv_bfloat16 z = __float2bfloat16(0.f);
        for (int k = EBLK + 12; k < AGLD; k++) { g_Ag0[base + k] = z; g_Ag1[base + k] = z; }
    }
}

// ------------------------- GEMM engine (R6-proven 128x128, + K-mapping) ----
// 128x128 CTA tile, KTILE=64, 3-slot ring / 2 tiles in flight, ldmatrix,
// one __syncthreads per K-tile. 256 threads, warp grid 2Mx4N, warp tile 64x32.
#define TK 64
#define NSTG 3
#define STG_BYTES 32768          // A 16KB + B 16KB
#define GEMM_SMEM (NSTG * STG_BYTES)

enum { EPI_CTX = 0, EPI_TANH_SPLIT = 1, EPI_TANH_C = 2, EPI_GATES = 3, EPI_GELU = 4 };

__device__ __forceinline__ void lstm_cell(float* cbuf, __nv_bfloat16* outs, int row, int j,
                                          float gi, float gf, float gg, float go) {
    float cold = cbuf[(size_t)row * HID + j];
    float si = 1.f / (1.f + expf(-gi));
    float sf = 1.f / (1.f + expf(-gf));
    float so = 1.f / (1.f + expf(-go));
    float tg = tanhf(gg);
    float cn = sf * cold + si * tg;
    float h  = so * tanhf(cn);
    cbuf[(size_t)row * HID + j] = cn;
    outs[(size_t)row * AGLD + j]        = bhi(h);
    outs[(size_t)row * AGLD + 1024 + j] = blo(h);
}

template <int EPI>
__global__ void __launch_bounds__(256, 2)
gemm2(const __nv_bfloat16* __restrict__ A, int lda,
      const __nv_bfloat16* __restrict__ W, int ktot,
      int s1, int d1, int s2, int d2,        // K->A col mapping (per 64-tile)
      const float* __restrict__ aux,
      float* __restrict__ outf,
      __nv_bfloat16* __restrict__ outs,
      int nOut) {
    extern __shared__ __align__(1024) char smp[];
    const uint32_t sbase = (uint32_t)__cvta_generic_to_shared(smp);

    const int tid = threadIdx.x;
    const int lane = tid & 31, wid = tid >> 5;
    const int wm = wid >> 2, wn = wid & 3;
    const int m0 = blockIdx.y * 128, n0 = blockIdx.x * 128;
    const int nK = ktot / TK;

    float acc[4][4][4];
#pragma unroll
    for (int a = 0; a < 4; a++)
#pragma unroll
        for (int b = 0; b < 4; b++)
#pragma unroll
            for (int c = 0; c < 4; c++) acc[a][b][c] = 0.f;

    auto fill = [&](int kt) {
        int slot = kt % NSTG;
        uint32_t sA = sbase + slot * STG_BYTES;
        uint32_t sB = sA + 16384;
        int k0 = kt * TK;
        int cb = (k0 < s1) ? k0 : ((k0 < s2) ? k0 - d1 : k0 - d2);
#pragma unroll
        for (int t = 0; t < 4; t++) {
            int c = tid + t * 256;
            int row = c >> 3, ch = c & 7;
            cpasync16(sA + SW128(row * 128 + ch * 16),
                      A + (size_t)(m0 + row) * lda + cb + ch * 8);
        }
#pragma unroll
        for (int t = 0; t < 4; t++) {
            int c = tid + t * 256;
            int row = c >> 3, ch = c & 7;
            cpasync16(sB + SW128(row * 128 + ch * 16),
                      W + (size_t)(n0 + row) * ktot + k0 + ch * 8);
        }
        asm volatile("cp.async.commit_group;\n");
    };

    // prologue: 2 tiles in flight
    fill(0);
    if (nK > 1) fill(1);

    const int g  = lane >> 3;
    const int lr = lane & 7;

    for (int kt = 0; kt < nK; kt++) {
        if (kt + 1 < nK) asm volatile("cp.async.wait_group 1;\n");
        else             asm volatile("cp.async.wait_group 0;\n");
        __syncthreads();                       // all warps done reading slot (kt-1)%3
        if (kt + 2 < nK) fill(kt + 2);         // safe: overwrites slot (kt-1)%3

        int slot = kt % NSTG;
        uint32_t sA = sbase + slot * STG_BYTES;
        uint32_t sB = sA + 16384;

#pragma unroll
        for (int ks = 0; ks < 4; ks++) {
            uint32_t a[4][4], b[2][4];
#pragma unroll
            for (int mf = 0; mf < 4; mf++) {
                int row = wm * 64 + mf * 16 + lr + ((g & 1) << 3);
                ldsm4(a[mf], sA + SW128(row * 128 + ks * 32 + ((g >> 1) << 4)));
            }
#pragma unroll
            for (int nf = 0; nf < 2; nf++) {
                int row = wn * 32 + nf * 16 + lr + ((g >> 1) << 3);
                ldsm4(b[nf], sB + SW128(row * 128 + ks * 32 + ((g & 1) << 4)));
            }
#pragma unroll
            for (int mf = 0; mf < 4; mf++) {
#pragma unroll
                for (int nf = 0; nf < 2; nf++) {
                    mma16816(acc[mf][2 * nf],     a[mf], &b[nf][0]);
                    mma16816(acc[mf][2 * nf + 1], a[mf], &b[nf][2]);
                }
            }
        }
    }

    // ------------------------- epilogue -------------------------
#pragma unroll
    for (int mt = 0; mt < 4; mt++) {
#pragma unroll
        for (int nt = 0; nt < 4; nt++) {
            int r = m0 + wm * 64 + mt * 16 + (lane >> 2);
            int n = n0 + wn * 32 + nt * 8 + (lane & 3) * 2;
            float v0 = acc[mt][nt][0], v1 = acc[mt][nt][1];
            float v2 = acc[mt][nt][2], v3 = acc[mt][nt][3];

            if (EPI == EPI_CTX) {
                outf[(size_t)r * nOut + n]           = v0 + aux[n];
                outf[(size_t)r * nOut + n + 1]       = v1 + aux[n + 1];
                outf[(size_t)(r + 8) * nOut + n]     = v2 + aux[n];
                outf[(size_t)(r + 8) * nOut + n + 1] = v3 + aux[n + 1];
            } else if (EPI == EPI_TANH_C) {
                outf[(size_t)r * nOut + n]           = tanhf(v0 + aux[n]);
                outf[(size_t)r * nOut + n + 1]       = tanhf(v1 + aux[n + 1]);
                outf[(size_t)(r + 8) * nOut + n]     = tanhf(v2 + aux[n]);
                outf[(size_t)(r + 8) * nOut + n + 1] = tanhf(v3 + aux[n + 1]);
            } else if (EPI == EPI_TANH_SPLIT) {
#pragma unroll
                for (int q = 0; q < 4; q++) {
                    int rr = (q >= 2) ? r + 8 : r;
                    int nn = n + (q & 1);
                    float v = (q == 0) ? v0 : (q == 1) ? v1 : (q == 2) ? v2 : v3;
                    float h = tanhf(v + aux[nn]);
                    outs[(size_t)rr * AGLD + nn]        = bhi(h);
                    outs[(size_t)rr * AGLD + 1024 + nn] = blo(h);
                }
            } else if (EPI == EPI_GELU) {
#pragma unroll
                for (int q = 0; q < 4; q++) {
                    int rr = (q >= 2) ? r + 8 : r;
                    int nn = n + (q & 1);
                    float v = (q == 0) ? v0 : (q == 1) ? v1 : (q == 2) ? v2 : v3;
                    float u = v + aux[nn];
                    outf[(size_t)rr * nOut + nn] = 0.5f * u * (1.f + erff(u * 0.70710678118654752f));
                }
            } else { // EPI_GATES
                float w0 = v0 + aux[(size_t)r * N4 + n];
                float w1 = v1 + aux[(size_t)r * N4 + n + 1];
                float w2 = v2 + aux[(size_t)(r + 8) * N4 + n];
                float w3 = v3 + aux[(size_t)(r + 8) * N4 + n + 1];
                float u0 = __shfl_xor_sync(0xffffffffu, w0, 1);
                float u1 = __shfl_xor_sync(0xffffffffu, w1, 1);
                float u2 = __shfl_xor_sync(0xffffffffu, w2, 1);
                float u3 = __shfl_xor_sync(0xffffffffu, w3, 1);
                if (!(lane & 1)) {   // even lanes own (i,f); lane^1 holds (g,o)
                    int j = n >> 2;
                    lstm_cell(outf, outs, r, j, w0, w1, u0, u1);
                    lstm_cell(outf, outs, r + 8, j, w2, w3, u2, u3);
                }
            }
        }
    }
}

// ------------------------- LayerNorm (warp per row) -------------------------
__global__ void ln_kernel(const __nv_bfloat16* __restrict__ Ag,
                          const float* __restrict__ gam, const float* __restrict__ bet) {
    int warp = (blockIdx.x * blockDim.x + threadIdx.x) >> 5;
    int lane = threadIdx.x & 31;
    if (warp >= BATCH) return;
    size_t base = (size_t)warp * AGLD;
    float h[32];
    float s = 0.f, ss = 0.f;
#pragma unroll
    for (int i = 0; i < 32; i++) {
        int k = lane + 32 * i;
        float v = __bfloat162float(Ag[base + k]) + __bfloat162float(Ag[base + 1024 + k]);
        h[i] = v; s += v; ss += v * v;
    }
#pragma unroll
    for (int o = 16; o; o >>= 1) {
        s  += __shfl_xor_sync(0xffffffffu, s, o);
        ss += __shfl_xor_sync(0xffffffffu, ss, o);
    }
    float mu = s * (1.f / HID);
    float var = ss * (1.f / HID) - mu * mu;
    float inv = rsqrtf(var + 1e-5f);
    size_t ob = (size_t)warp * AFLD;
#pragma unroll
    for (int i = 0; i < 32; i++) {
        int k = lane + 32 * i;
        float y = (h[i] - mu) * inv * gam[k] + bet[k];
        g_Af[ob + k]        = bhi(y);
        g_Af[ob + 1024 + k] = blo(y);
    }
}

// ------------------------- delta / pos head (warp per row) -------------------------
__global__ void delta_kernel(const float* __restrict__ W2, const float* __restrict__ b2,
                             float* __restrict__ out, int t, __nv_bfloat16* __restrict__ AgN) {
    int warp = (blockIdx.x * blockDim.x + threadIdx.x) >> 5;
    int lane = threadIdx.x & 31;
    if (warp >= BATCH) return;
    const float* y = g_y2 + (size_t)warp * HID;
    float a0 = 0.f, a1 = 0.f;
#pragma unroll
    for (int i = 0; i < 32; i++) {
        int k = lane + 32 * i;
        float v = y[k];
        a0 += v * W2[k];
        a1 += v * W2[HID + k];
    }
#pragma unroll
    for (int o = 16; o; o >>= 1) {
        a0 += __shfl_xor_sync(0xffffffffu, a0, o);
        a1 += __shfl_xor_sync(0xffffffffu, a1, o);
    }
    if (lane == 0) {
        float d0 = a0 + b2[0], d1 = a1 + b2[1];
        float p0 = g_pos[warp * 2 + 0] + d0;
        float p1 = g_pos[warp * 2 + 1] + d1;
        g_pos[warp * 2 + 0] = p0;
        g_pos[warp * 2 + 1] = p1;
        out[(size_t)warp * (TSTEPS * 2) + t * 2 + 0] = p0;
        out[(size_t)warp * (TSTEPS * 2) + t * 2 + 1] = p1;
        float nn = fmaxf(sqrtf(d0 * d0 + d1 * d1), 1e-6f);
        float e[4] = {d0, d1, d0 / nn, d1 / nn};
        size_t base = (size_t)warp * AGLD;
#pragma unroll
        for (int q = 0; q < 4; q++) {
            AgN[base + EBLK + q]     = bhi(e[q]);
            AgN[base + EBLK + 4 + q] = blo(e[q]);
            AgN[base + EBLK + 8 + q] = bhi(e[q]);
        }
    }
}

// ------------------------- host -------------------------
static inline int nb(long n) { return (int)((n + 255) / 256); }

extern "C" void kernel_launch(void* const* d_in, const int* in_sizes, int n_in,
                              void* d_out, int out_size) {
    const float* context    = (const float*)d_in[0];
    const float* last_pos   = (const float*)d_in[1];
    const float* last_delta = (const float*)d_in[2];
    const float* Wh   = (const float*)d_in[3];
    const float* bh   = (const float*)d_in[4];
    const float* Wc   = (const float*)d_in[5];
    const float* bc   = (const float*)d_in[6];
    const float* W_ih = (const float*)d_in[7];
    const float* b_ih = (const float*)d_in[8];
    const float* W_hh = (const float*)d_in[9];
    const float* b_hh = (const float*)d_in[10];
    const float* ln_g = (const float*)d_in[11];
    const float* ln_b = (const float*)d_in[12];
    const float* W1   = (const float*)d_in[13];
    const float* b1   = (const float*)d_in[14];
    const float* W2   = (const float*)d_in[15];
    const float* b2   = (const float*)d_in[16];
    float* out = (float*)d_out;

    __nv_bfloat16 *pCtxs, *pAg0, *pAg1, *pAf, *pWg, *pWc4, *pWhh, *pWcc, *pW1s;
    float *pGctx, *pC, *pY2, *pBsum;
    cudaGetSymbolAddress((void**)&pCtxs, g_ctxs);
    cudaGetSymbolAddress((void**)&pAg0, g_Ag0);
    cudaGetSymbolAddress((void**)&pAg1, g_Ag1);
    cudaGetSymbolAddress((void**)&pAf,  g_Af);
    cudaGetSymbolAddress((void**)&pWg,  g_Wg);
    cudaGetSymbolAddress((void**)&pWc4, g_Wc4);
    cudaGetSymbolAddress((void**)&pWhh, g_Whh);
    cudaGetSymbolAddress((void**)&pWcc, g_Wcc);
    cudaGetSymbolAddress((void**)&pW1s, g_W1s);
    cudaGetSymbolAddress((void**)&pGctx, g_gctx);
    cudaGetSymbolAddress((void**)&pC,   g_c);
    cudaGetSymbolAddress((void**)&pY2,  g_y2);
    cudaGetSymbolAddress((void**)&pBsum, g_bsum);

    cudaFuncSetAttribute(gemm2<EPI_CTX>,        cudaFuncAttributeMaxDynamicSharedMemorySize, GEMM_SMEM);
    cudaFuncSetAttribute(gemm2<EPI_TANH_SPLIT>, cudaFuncAttributeMaxDynamicSharedMemorySize, GEMM_SMEM);
    cudaFuncSetAttribute(gemm2<EPI_TANH_C>,     cudaFuncAttributeMaxDynamicSharedMemorySize, GEMM_SMEM);
    cudaFuncSetAttribute(gemm2<EPI_GATES>,      cudaFuncAttributeMaxDynamicSharedMemorySize, GEMM_SMEM);
    cudaFuncSetAttribute(gemm2<EPI_GELU>,       cudaFuncAttributeMaxDynamicSharedMemorySize, GEMM_SMEM);

    const int BIG = 1 << 30;

    // launch #0, #1: prep (merged so launch #5 = first gates GEMM for ncu -s 5)
    {
        long tot = (long)N4 * KG + (long)N4 * KC + N4
                 + (long)HID * CTXK * 2 + (long)HID * HID;
        prep_weights<<<nb(tot), 256>>>(W_hh, W_ih, b_ih, b_hh, Wh, Wc, W1);
    }
    {
        long tot = (long)BATCH * CTXK + BATCH;
        prep_data<<<nb(tot), 256>>>(context, last_pos, last_delta);
    }

    dim3 blk(256);
    dim3 grid_n4(N4 / 128, BATCH / 128);   // (32,128)
    dim3 grid_h(HID / 128, BATCH / 128);   // (8,128)

    // #2 gates_ctx ; #3 hidden init ; #4 cell init
    gemm2<EPI_CTX><<<grid_n4, blk, GEMM_SMEM>>>(pCtxs, ACLD, pWc4, KC, 1024, 1024, BIG, 0,
                                                pBsum, pGctx, nullptr, N4);
    gemm2<EPI_TANH_SPLIT><<<grid_h, blk, GEMM_SMEM>>>(pCtxs, ACLD, pWhh, KC, 1024, 1024, BIG, 0,
                                                      bh, nullptr, pAg0, HID);
    gemm2<EPI_TANH_C><<<grid_h, blk, GEMM_SMEM>>>(pCtxs, ACLD, pWcc, KC, 1024, 1024, BIG, 0,
                                                  bc, pC, nullptr, HID);

    __nv_bfloat16* Ag[2] = {pAg0, pAg1};
    for (int t = 0; t < TSTEPS; t++) {
        int cur = t & 1, nxt = cur ^ 1;
        gemm2<EPI_GATES><<<grid_n4, blk, GEMM_SMEM>>>(Ag[cur], AGLD, pWg, KG, 2048, 2048, 3072, 1024,
                                                      pGctx, pC, Ag[nxt], N4);
        ln_kernel<<<BATCH / 8, 256>>>(Ag[nxt], ln_g, ln_b);
        gemm2<EPI_GELU><<<grid_h, blk, GEMM_SMEM>>>(pAf, AFLD, pW1s, KF, 2048, 2048, BIG, 0,
                                                    b1, pY2, nullptr, HID);
        delta_kernel<<<BATCH / 8, 256>>>(W2, b2, out, t, Ag[nxt]);
    }
}

// round 9
// speedup vs baseline: 1.9140x; 1.3342x over previous
#include <cuda_runtime.h>
#include <cuda_fp16.h>
#include <math.h>
#include <stdint.h>

#define BATCH   16384
#define HID     1024
#define CTXK    512
#define N4      4096
#define TSTEPS  60
#define INW     516     // W_ih row width (C+4)

// fp16 2-term split for per-step GEMMs: x*W ~= (x_hi + x_lo) * W_hi
// gates GEMM: A row = K row = [h_hi(1024) | h_lo(1024) | eblk(64)] -> KG=2112=33*64
//   eblk = [e_hi(4) | e_lo(4) | zeros(56)]
#define AGLD    2112
#define EBLK    2048
#define KG      2112
// ffn GEMM: A row = K row = [y_hi(1024) | y_lo(1024)] -> KF=2048
#define AFLD    2048
#define KF      2048
// context GEMMs (one-time, 3-term fp16): A row = [c_hi(512)|c_lo(512)];
//   K = [c_hi | c_lo | c_hi(re-read)] = 1536 ; W = [W_hi|W_hi|W_lo]
#define ACLD    1024
#define KC      1536

// ------------------------- scratch (device globals) -------------------------
__device__ __align__(256) float   g_gctx[(size_t)BATCH * N4];
__device__ __align__(256) __half  g_Ag0[(size_t)BATCH * AGLD];
__device__ __align__(256) __half  g_Ag1[(size_t)BATCH * AGLD];
__device__ __align__(256) __half  g_Af [(size_t)BATCH * AFLD];
__device__ __align__(256) __half  g_ctxs[(size_t)BATCH * ACLD];
__device__ __align__(256) float   g_c  [(size_t)BATCH * HID];
__device__ __align__(256) float   g_y2 [(size_t)BATCH * HID];
__device__ __align__(256) float   g_pos[(size_t)BATCH * 2];
__device__ __align__(256) __half  g_Wg  [(size_t)N4 * KG];
__device__ __align__(256) __half  g_Wc4 [(size_t)N4 * KC];
__device__ __align__(256) __half  g_Whh [(size_t)HID * KC];
__device__ __align__(256) __half  g_Wcc [(size_t)HID * KC];
__device__ __align__(256) __half  g_W1s [(size_t)HID * KF];
__device__ __align__(256) float   g_bsum[N4];

// ------------------------- low-level helpers -------------------------
#define SW128(b) ((b) ^ (((b) >> 3) & 0x70))

__device__ __forceinline__ void cpasync16(uint32_t dst, const void* src) {
    asm volatile("cp.async.cg.shared.global [%0],[%1],16;\n" :: "r"(dst), "l"(src));
}
__device__ __forceinline__ void ldsm4(uint32_t* r, uint32_t addr) {
    asm volatile("ldmatrix.sync.aligned.m8n8.x4.shared.b16 {%0,%1,%2,%3}, [%4];"
                 : "=r"(r[0]), "=r"(r[1]), "=r"(r[2]), "=r"(r[3]) : "r"(addr));
}
__device__ __forceinline__ void mma16816(float* c, const uint32_t* a, const uint32_t* b) {
    asm volatile(
        "mma.sync.aligned.m16n8k16.row.col.f32.f16.f16.f32 "
        "{%0,%1,%2,%3},{%4,%5,%6,%7},{%8,%9},{%0,%1,%2,%3};\n"
        : "+f"(c[0]), "+f"(c[1]), "+f"(c[2]), "+f"(c[3])
        : "r"(a[0]), "r"(a[1]), "r"(a[2]), "r"(a[3]), "r"(b[0]), "r"(b[1]));
}
__device__ __forceinline__ __half hhi(float v) { return __float2half_rn(v); }
__device__ __forceinline__ __half hlo(float v) {
    return __float2half_rn(v - __half2float(__float2half_rn(v)));
}

// ------------------------- prep kernels -------------------------
__global__ void prep_weights(const float* __restrict__ Whh, const float* __restrict__ Wih,
                             const float* __restrict__ b_ih, const float* __restrict__ b_hh,
                             const float* __restrict__ Wh, const float* __restrict__ Wc,
                             const float* __restrict__ W1) {
    const long n_wg = (long)N4 * KG;          // gates W, per-output-slot
    const long n_wc = (long)N4 * KC;          // ctx W_ih part, per-output-slot
    const long n_s  = (long)HID * CTXK;       // Wh / Wc, per-source
    const long n_w1 = (long)HID * HID;        // W1, per-source
    long i = (long)blockIdx.x * blockDim.x + threadIdx.x;

    if (i < n_wg) {   // [Whh_hi | Whh_hi | eW];  eW = [We_hi(4)|We_hi(4)|0]
        int np = (int)(i / KG), k = (int)(i % KG);
        int r = (np & 3) * HID + (np >> 2);
        float w = 0.f;
        if (k < 1024)        w = Whh[(size_t)r * HID + k];
        else if (k < 2048)   w = Whh[(size_t)r * HID + (k - 1024)];
        else {
            int q = k - 2048;
            if (q < 4)        w = Wih[(size_t)r * INW + CTXK + q];
            else if (q < 8)   w = Wih[(size_t)r * INW + CTXK + (q - 4)];
        }
        g_Wg[(size_t)np * KG + k] = hhi(w);
        return;
    }
    i -= n_wg;
    if (i < n_wc) {   // W_ih ctx part (3-term): [hi(512)|hi(512)|lo(512)]
        int np = (int)(i / KC), k = (int)(i % KC);
        int r = (np & 3) * HID + (np >> 2);
        int src = (k < 512) ? k : (k < 1024 ? k - 512 : k - 1024);
        float w = Wih[(size_t)r * INW + src];
        g_Wc4[(size_t)np * KC + k] = (k < 1024) ? hhi(w) : hlo(w);
        return;
    }
    i -= n_wc;
    if (i < N4) {
        int r = ((int)i & 3) * HID + ((int)i >> 2);
        g_bsum[i] = b_ih[r] + b_hh[r];
        return;
    }
    i -= N4;
    if (i < n_s) {    // Wh (3-term): [hi|hi|lo]
        int r = (int)(i / CTXK), k = (int)(i % CTXK);
        float w = Wh[(size_t)r * CTXK + k];
        size_t b = (size_t)r * KC;
        g_Whh[b + k] = hhi(w); g_Whh[b + 512 + k] = hhi(w); g_Whh[b + 1024 + k] = hlo(w);
        return;
    }
    i -= n_s;
    if (i < n_s) {    // Wc (3-term)
        int r = (int)(i / CTXK), k = (int)(i % CTXK);
        float w = Wc[(size_t)r * CTXK + k];
        size_t b = (size_t)r * KC;
        g_Wcc[b + k] = hhi(w); g_Wcc[b + 512 + k] = hhi(w); g_Wcc[b + 1024 + k] = hlo(w);
        return;
    }
    i -= n_s;
    if (i < n_w1) {   // W1 (2-term): [hi|hi]
        int r = (int)(i / HID), k = (int)(i % HID);
        float w = W1[(size_t)r * HID + k];
        size_t b = (size_t)r * KF;
        g_W1s[b + k] = hhi(w); g_W1s[b + 1024 + k] = hhi(w);
    }
}

__global__ void prep_data(const float* __restrict__ ctx,
                          const float* __restrict__ last_pos,
                          const float* __restrict__ last_delta) {
    const long n_cs = (long)BATCH * CTXK;
    long i = (long)blockIdx.x * blockDim.x + threadIdx.x;
    if (i < n_cs) {
        int b = (int)(i / CTXK), k = (int)(i % CTXK);
        float v = ctx[i];
        g_ctxs[(size_t)b * ACLD + k]       = hhi(v);
        g_ctxs[(size_t)b * ACLD + 512 + k] = hlo(v);
        return;
    }
    i -= n_cs;
    if (i < BATCH) {
        int b = (int)i;
        g_pos[b * 2 + 0] = last_pos[b * 2 + 0];
        g_pos[b * 2 + 1] = last_pos[b * 2 + 1];
        float d0 = last_delta[b * 2 + 0], d1 = last_delta[b * 2 + 1];
        float nn = fmaxf(sqrtf(d0 * d0 + d1 * d1), 1e-6f);
        float e[4] = {d0, d1, d0 / nn, d1 / nn};
        size_t base = (size_t)b * AGLD;
#pragma unroll
        for (int q = 0; q < 4; q++) {
            g_Ag0[base + EBLK + q]     = hhi(e[q]);
            g_Ag0[base + EBLK + 4 + q] = hlo(e[q]);
        }
        __half z = __float2half(0.f);
        for (int k = EBLK + 8; k < AGLD; k++) { g_Ag0[base + k] = z; g_Ag1[base + k] = z; }
    }
}

// ------------------------- GEMM engine (R6/R8-proven 128x128) -------------------------
// 128x128 CTA tile, KTILE=64, 3-slot ring / 2 tiles in flight, ldmatrix,
// one __syncthreads per K-tile. 256 threads, warp grid 2Mx4N, warp tile 64x32.
#define TK 64
#define NSTG 3
#define STG_BYTES 32768          // A 16KB + B 16KB
#define GEMM_SMEM (NSTG * STG_BYTES)

enum { EPI_CTX = 0, EPI_TANH_SPLIT = 1, EPI_TANH_C = 2, EPI_GATES = 3, EPI_GELU = 4 };

__device__ __forceinline__ void lstm_cell(float* cbuf, __half* outs, int row, int j,
                                          float gi, float gf, float gg, float go) {
    float cold = cbuf[(size_t)row * HID + j];
    float si = 1.f / (1.f + expf(-gi));
    float sf = 1.f / (1.f + expf(-gf));
    float so = 1.f / (1.f + expf(-go));
    float tg = tanhf(gg);
    float cn = sf * cold + si * tg;
    float h  = so * tanhf(cn);
    cbuf[(size_t)row * HID + j] = cn;
    outs[(size_t)row * AGLD + j]        = hhi(h);
    outs[(size_t)row * AGLD + 1024 + j] = hlo(h);
}

template <int EPI>
__global__ void __launch_bounds__(256, 2)
gemm2(const __half* __restrict__ A, int lda,
      const __half* __restrict__ W, int ktot,
      int s1, int d1,                        // K->A col mapping (per 64-tile)
      const float* __restrict__ aux,
      float* __restrict__ outf,
      __half* __restrict__ outs,
      int nOut) {
    extern __shared__ __align__(1024) char smp[];
    const uint32_t sbase = (uint32_t)__cvta_generic_to_shared(smp);

    const int tid = threadIdx.x;
    const int lane = tid & 31, wid = tid >> 5;
    const int wm = wid >> 2, wn = wid & 3;
    const int m0 = blockIdx.y * 128, n0 = blockIdx.x * 128;
    const int nK = ktot / TK;

    float acc[4][4][4];
#pragma unroll
    for (int a = 0; a < 4; a++)
#pragma unroll
        for (int b = 0; b < 4; b++)
#pragma unroll
            for (int c = 0; c < 4; c++) acc[a][b][c] = 0.f;

    auto fill = [&](int kt) {
        int slot = kt % NSTG;
        uint32_t sA = sbase + slot * STG_BYTES;
        uint32_t sB = sA + 16384;
        int k0 = kt * TK;
        int cb = (k0 < s1) ? k0 : k0 - d1;
#pragma unroll
        for (int t = 0; t < 4; t++) {
            int c = tid + t * 256;
            int row = c >> 3, ch = c & 7;
            cpasync16(sA + SW128(row * 128 + ch * 16),
                      A + (size_t)(m0 + row) * lda + cb + ch * 8);
        }
#pragma unroll
        for (int t = 0; t < 4; t++) {
            int c = tid + t * 256;
            int row = c >> 3, ch = c & 7;
            cpasync16(sB + SW128(row * 128 + ch * 16),
                      W + (size_t)(n0 + row) * ktot + k0 + ch * 8);
        }
        asm volatile("cp.async.commit_group;\n");
    };

    // prologue: 2 tiles in flight
    fill(0);
    if (nK > 1) fill(1);

    const int g  = lane >> 3;
    const int lr = lane & 7;

    for (int kt = 0; kt < nK; kt++) {
        if (kt + 1 < nK) asm volatile("cp.async.wait_group 1;\n");
        else             asm volatile("cp.async.wait_group 0;\n");
        __syncthreads();                       // all warps done reading slot (kt-1)%3
        if (kt + 2 < nK) fill(kt + 2);         // safe: overwrites slot (kt-1)%3

        int slot = kt % NSTG;
        uint32_t sA = sbase + slot * STG_BYTES;
        uint32_t sB = sA + 16384;

#pragma unroll
        for (int ks = 0; ks < 4; ks++) {
            uint32_t a[4][4], b[2][4];
#pragma unroll
            for (int mf = 0; mf < 4; mf++) {
                int row = wm * 64 + mf * 16 + lr + ((g & 1) << 3);
                ldsm4(a[mf], sA + SW128(row * 128 + ks * 32 + ((g >> 1) << 4)));
            }
#pragma unroll
            for (int nf = 0; nf < 2; nf++) {
                int row = wn * 32 + nf * 16 + lr + ((g >> 1) << 3);
                ldsm4(b[nf], sB + SW128(row * 128 + ks * 32 + ((g & 1) << 4)));
            }
#pragma unroll
            for (int mf = 0; mf < 4; mf++) {
#pragma unroll
                for (int nf = 0; nf < 2; nf++) {
                    mma16816(acc[mf][2 * nf],     a[mf], &b[nf][0]);
                    mma16816(acc[mf][2 * nf + 1], a[mf], &b[nf][2]);
                }
            }
        }
    }

    // ------------------------- epilogue -------------------------
#pragma unroll
    for (int mt = 0; mt < 4; mt++) {
#pragma unroll
        for (int nt = 0; nt < 4; nt++) {
            int r = m0 + wm * 64 + mt * 16 + (lane >> 2);
            int n = n0 + wn * 32 + nt * 8 + (lane & 3) * 2;
            float v0 = acc[mt][nt][0], v1 = acc[mt][nt][1];
            float v2 = acc[mt][nt][2], v3 = acc[mt][nt][3];

            if (EPI == EPI_CTX) {
                outf[(size_t)r * nOut + n]           = v0 + aux[n];
                outf[(size_t)r * nOut + n + 1]       = v1 + aux[n + 1];
                outf[(size_t)(r + 8) * nOut + n]     = v2 + aux[n];
                outf[(size_t)(r + 8) * nOut + n + 1] = v3 + aux[n + 1];
            } else if (EPI == EPI_TANH_C) {
                outf[(size_t)r * nOut + n]           = tanhf(v0 + aux[n]);
                outf[(size_t)r * nOut + n + 1]       = tanhf(v1 + aux[n + 1]);
                outf[(size_t)(r + 8) * nOut + n]     = tanhf(v2 + aux[n]);
                outf[(size_t)(r + 8) * nOut + n + 1] = tanhf(v3 + aux[n + 1]);
            } else if (EPI == EPI_TANH_SPLIT) {
#pragma unroll
                for (int q = 0; q < 4; q++) {
                    int rr = (q >= 2) ? r + 8 : r;
                    int nn = n + (q & 1);
                    float v = (q == 0) ? v0 : (q == 1) ? v1 : (q == 2) ? v2 : v3;
                    float h = tanhf(v + aux[nn]);
                    outs[(size_t)rr * AGLD + nn]        = hhi(h);
                    outs[(size_t)rr * AGLD + 1024 + nn] = hlo(h);
                }
            } else if (EPI == EPI_GELU) {
#pragma unroll
                for (int q = 0; q < 4; q++) {
                    int rr = (q >= 2) ? r + 8 : r;
                    int nn = n + (q & 1);
                    float v = (q == 0) ? v0 : (q == 1) ? v1 : (q == 2) ? v2 : v3;
                    float u = v + aux[nn];
                    outf[(size_t)rr * nOut + nn] = 0.5f * u * (1.f + erff(u * 0.70710678118654752f));
                }
            } else { // EPI_GATES
                float w0 = v0 + aux[(size_t)r * N4 + n];
                float w1 = v1 + aux[(size_t)r * N4 + n + 1];
                float w2 = v2 + aux[(size_t)(r + 8) * N4 + n];
                float w3 = v3 + aux[(size_t)(r + 8) * N4 + n + 1];
                float u0 = __shfl_xor_sync(0xffffffffu, w0, 1);
                float u1 = __shfl_xor_sync(0xffffffffu, w1, 1);
                float u2 = __shfl_xor_sync(0xffffffffu, w2, 1);
                float u3 = __shfl_xor_sync(0xffffffffu, w3, 1);
                if (!(lane & 1)) {   // even lanes own (i,f); lane^1 holds (g,o)
                    int j = n >> 2;
                    lstm_cell(outf, outs, r, j, w0, w1, u0, u1);
                    lstm_cell(outf, outs, r + 8, j, w2, w3, u2, u3);
                }
            }
        }
    }
}

// ------------------------- LayerNorm (warp per row) -------------------------
__global__ void ln_kernel(const __half* __restrict__ Ag,
                          const float* __restrict__ gam, const float* __restrict__ bet) {
    int warp = (blockIdx.x * blockDim.x + threadIdx.x) >> 5;
    int lane = threadIdx.x & 31;
    if (warp >= BATCH) return;
    size_t base = (size_t)warp * AGLD;
    float h[32];
    float s = 0.f, ss = 0.f;
#pragma unroll
    for (int i = 0; i < 32; i++) {
        int k = lane + 32 * i;
        float v = __half2float(Ag[base + k]) + __half2float(Ag[base + 1024 + k]);
        h[i] = v; s += v; ss += v * v;
    }
#pragma unroll
    for (int o = 16; o; o >>= 1) {
        s  += __shfl_xor_sync(0xffffffffu, s, o);
        ss += __shfl_xor_sync(0xffffffffu, ss, o);
    }
    float mu = s * (1.f / HID);
    float var = ss * (1.f / HID) - mu * mu;
    float inv = rsqrtf(var + 1e-5f);
    size_t ob = (size_t)warp * AFLD;
#pragma unroll
    for (int i = 0; i < 32; i++) {
        int k = lane + 32 * i;
        float y = (h[i] - mu) * inv * gam[k] + bet[k];
        g_Af[ob + k]        = hhi(y);
        g_Af[ob + 1024 + k] = hlo(y);
    }
}

// ------------------------- delta / pos head (warp per row) -------------------------
__global__ void delta_kernel(const float* __restrict__ W2, const float* __restrict__ b2,
                             float* __restrict__ out, int t, __half* __restrict__ AgN) {
    int warp = (blockIdx.x * blockDim.x + threadIdx.x) >> 5;
    int lane = threadIdx.x & 31;
    if (warp >= BATCH) return;
    const float* y = g_y2 + (size_t)warp * HID;
    float a0 = 0.f, a1 = 0.f;
#pragma unroll
    for (int i = 0; i < 32; i++) {
        int k = lane + 32 * i;
        float v = y[k];
        a0 += v * W2[k];
        a1 += v * W2[HID + k];
    }
#pragma unroll
    for (int o = 16; o; o >>= 1) {
        a0 += __shfl_xor_sync(0xffffffffu, a0, o);
        a1 += __shfl_xor_sync(0xffffffffu, a1, o);
    }
    if (lane == 0) {
        float d0 = a0 + b2[0], d1 = a1 + b2[1];
        float p0 = g_pos[warp * 2 + 0] + d0;
        float p1 = g_pos[warp * 2 + 1] + d1;
        g_pos[warp * 2 + 0] = p0;
        g_pos[warp * 2 + 1] = p1;
        out[(size_t)warp * (TSTEPS * 2) + t * 2 + 0] = p0;
        out[(size_t)warp * (TSTEPS * 2) + t * 2 + 1] = p1;
        float nn = fmaxf(sqrtf(d0 * d0 + d1 * d1), 1e-6f);
        float e[4] = {d0, d1, d0 / nn, d1 / nn};
        size_t base = (size_t)warp * AGLD;
#pragma unroll
        for (int q = 0; q < 4; q++) {
            AgN[base + EBLK + q]     = hhi(e[q]);
            AgN[base + EBLK + 4 + q] = hlo(e[q]);
        }
    }
}

// ------------------------- host -------------------------
static inline int nb(long n) { return (int)((n + 255) / 256); }

extern "C" void kernel_launch(void* const* d_in, const int* in_sizes, int n_in,
                              void* d_out, int out_size) {
    const float* context    = (const float*)d_in[0];
    const float* last_pos   = (const float*)d_in[1];
    const float* last_delta = (const float*)d_in[2];
    const float* Wh   = (const float*)d_in[3];
    const float* bh   = (const float*)d_in[4];
    const float* Wc   = (const float*)d_in[5];
    const float* bc   = (const float*)d_in[6];
    const float* W_ih = (const float*)d_in[7];
    const float* b_ih = (const float*)d_in[8];
    const float* W_hh = (const float*)d_in[9];
    const float* b_hh = (const float*)d_in[10];
    const float* ln_g = (const float*)d_in[11];
    const float* ln_b = (const float*)d_in[12];
    const float* W1   = (const float*)d_in[13];
    const float* b1   = (const float*)d_in[14];
    const float* W2   = (const float*)d_in[15];
    const float* b2   = (const float*)d_in[16];
    float* out = (float*)d_out;

    __half *pCtxs, *pAg0, *pAg1, *pAf, *pWg, *pWc4, *pWhh, *pWcc, *pW1s;
    float *pGctx, *pC, *pY2, *pBsum;
    cudaGetSymbolAddress((void**)&pCtxs, g_ctxs);
    cudaGetSymbolAddress((void**)&pAg0, g_Ag0);
    cudaGetSymbolAddress((void**)&pAg1, g_Ag1);
    cudaGetSymbolAddress((void**)&pAf,  g_Af);
    cudaGetSymbolAddress((void**)&pWg,  g_Wg);
    cudaGetSymbolAddress((void**)&pWc4, g_Wc4);
    cudaGetSymbolAddress((void**)&pWhh, g_Whh);
    cudaGetSymbolAddress((void**)&pWcc, g_Wcc);
    cudaGetSymbolAddress((void**)&pW1s, g_W1s);
    cudaGetSymbolAddress((void**)&pGctx, g_gctx);
    cudaGetSymbolAddress((void**)&pC,   g_c);
    cudaGetSymbolAddress((void**)&pY2,  g_y2);
    cudaGetSymbolAddress((void**)&pBsum, g_bsum);

    cudaFuncSetAttribute(gemm2<EPI_CTX>,        cudaFuncAttributeMaxDynamicSharedMemorySize, GEMM_SMEM);
    cudaFuncSetAttribute(gemm2<EPI_TANH_SPLIT>, cudaFuncAttributeMaxDynamicSharedMemorySize, GEMM_SMEM);
    cudaFuncSetAttribute(gemm2<EPI_TANH_C>,     cudaFuncAttributeMaxDynamicSharedMemorySize, GEMM_SMEM);
    cudaFuncSetAttribute(gemm2<EPI_GATES>,      cudaFuncAttributeMaxDynamicSharedMemorySize, GEMM_SMEM);
    cudaFuncSetAttribute(gemm2<EPI_GELU>,       cudaFuncAttributeMaxDynamicSharedMemorySize, GEMM_SMEM);

    const int BIG = 1 << 30;

    {
        long tot = (long)N4 * KG + (long)N4 * KC + N4
                 + (long)HID * CTXK * 2 + (long)HID * HID;
        prep_weights<<<nb(tot), 256>>>(W_hh, W_ih, b_ih, b_hh, Wh, Wc, W1);
    }
    {
        long tot = (long)BATCH * CTXK + BATCH;
        prep_data<<<nb(tot), 256>>>(context, last_pos, last_delta);
    }

    dim3 blk(256);
    dim3 grid_n4(N4 / 128, BATCH / 128);   // (32,128)
    dim3 grid_h(HID / 128, BATCH / 128);   // (8,128)

    // gates_ctx (3-term), hidden/cell init (3-term)
    gemm2<EPI_CTX><<<grid_n4, blk, GEMM_SMEM>>>(pCtxs, ACLD, pWc4, KC, 1024, 1024,
                                                pBsum, pGctx, nullptr, N4);
    gemm2<EPI_TANH_SPLIT><<<grid_h, blk, GEMM_SMEM>>>(pCtxs, ACLD, pWhh, KC, 1024, 1024,
                                                      bh, nullptr, pAg0, HID);
    gemm2<EPI_TANH_C><<<grid_h, blk, GEMM_SMEM>>>(pCtxs, ACLD, pWcc, KC, 1024, 1024,
                                                  bc, pC, nullptr, HID);

    __half* Ag[2] = {pAg0, pAg1};
    for (int t = 0; t < TSTEPS; t++) {
        int cur = t & 1, nxt = cur ^ 1;
        gemm2<EPI_GATES><<<grid_n4, blk, GEMM_SMEM>>>(Ag[cur], AGLD, pWg, KG, BIG, 0,
                                                      pGctx, pC, Ag[nxt], N4);
        ln_kernel<<<BATCH / 8, 256>>>(Ag[nxt], ln_g, ln_b);
        gemm2<EPI_GELU><<<grid_h, blk, GEMM_SMEM>>>(pAf, AFLD, pW1s, KF, BIG, 0,
                                                    b1, pY2, nullptr, HID);
        delta_kernel<<<BATCH / 8, 256>>>(W2, b2, out, t, Ag[nxt]);
    }
}

// round 10
// speedup vs baseline: 2.0709x; 1.0819x over previous
#include <cuda_runtime.h>
#include <cuda_fp16.h>
#include <math.h>
#include <stdint.h>

#define BATCH   16384
#define HID     1024
#define CTXK    512
#define N4      4096
#define TSTEPS  60
#define INW     516     // W_ih row width (C+4)

// fp16 2-term split for gates GEMM: x*W ~= (x_hi + x_lo) * W_hi
// gates GEMM: A row = K row = [h_hi(1024) | h_lo(1024) | eblk(64)] -> KG=2112=33*64
//   eblk = [e_hi(4) | e_lo(4) | zeros(56)]
#define AGLD    2112
#define EBLK    2048
#define KG      2112
// ffn GEMM (single-term fp16, non-recurrent path): A row = K row = [y(1024)]
#define AFLD    1024
#define KF      1024
// context GEMMs (one-time, 3-term fp16): A row = [c_hi(512)|c_lo(512)];
//   K = [c_hi | c_lo | c_hi(re-read)] = 1536 ; W = [W_hi|W_hi|W_lo]
#define ACLD    1024
#define KC      1536

// ------------------------- scratch (device globals) -------------------------
__device__ __align__(256) float   g_gctx[(size_t)BATCH * N4];
__device__ __align__(256) __half  g_Ag0[(size_t)BATCH * AGLD];
__device__ __align__(256) __half  g_Ag1[(size_t)BATCH * AGLD];
__device__ __align__(256) __half  g_Af [(size_t)BATCH * AFLD];
__device__ __align__(256) __half  g_ctxs[(size_t)BATCH * ACLD];
__device__ __align__(256) float   g_c  [(size_t)BATCH * HID];
__device__ __align__(256) float   g_y2 [(size_t)BATCH * HID];
__device__ __align__(256) float   g_pos[(size_t)BATCH * 2];
__device__ __align__(256) __half  g_Wg  [(size_t)N4 * KG];
__device__ __align__(256) __half  g_Wc4 [(size_t)N4 * KC];
__device__ __align__(256) __half  g_Whh [(size_t)HID * KC];
__device__ __align__(256) __half  g_Wcc [(size_t)HID * KC];
__device__ __align__(256) __half  g_W1s [(size_t)HID * KF];
__device__ __align__(256) float   g_bsum[N4];

// ------------------------- low-level helpers -------------------------
#define SW128(b) ((b) ^ (((b) >> 3) & 0x70))

__device__ __forceinline__ void cpasync16(uint32_t dst, const void* src) {
    asm volatile("cp.async.cg.shared.global [%0],[%1],16;\n" :: "r"(dst), "l"(src));
}
__device__ __forceinline__ void ldsm4(uint32_t* r, uint32_t addr) {
    asm volatile("ldmatrix.sync.aligned.m8n8.x4.shared.b16 {%0,%1,%2,%3}, [%4];"
                 : "=r"(r[0]), "=r"(r[1]), "=r"(r[2]), "=r"(r[3]) : "r"(addr));
}
__device__ __forceinline__ void mma16816(float* c, const uint32_t* a, const uint32_t* b) {
    asm volatile(
        "mma.sync.aligned.m16n8k16.row.col.f32.f16.f16.f32 "
        "{%0,%1,%2,%3},{%4,%5,%6,%7},{%8,%9},{%0,%1,%2,%3};\n"
        : "+f"(c[0]), "+f"(c[1]), "+f"(c[2]), "+f"(c[3])
        : "r"(a[0]), "r"(a[1]), "r"(a[2]), "r"(a[3]), "r"(b[0]), "r"(b[1]));
}
__device__ __forceinline__ __half hhi(float v) { return __float2half_rn(v); }
__device__ __forceinline__ __half hlo(float v) {
    return __float2half_rn(v - __half2float(__float2half_rn(v)));
}

// ------------------------- prep kernels -------------------------
__global__ void prep_weights(const float* __restrict__ Whh, const float* __restrict__ Wih,
                             const float* __restrict__ b_ih, const float* __restrict__ b_hh,
                             const float* __restrict__ Wh, const float* __restrict__ Wc,
                             const float* __restrict__ W1) {
    const long n_wg = (long)N4 * KG;
    const long n_wc = (long)N4 * KC;
    const long n_s  = (long)HID * CTXK;
    const long n_w1 = (long)HID * HID;
    long i = (long)blockIdx.x * blockDim.x + threadIdx.x;

    if (i < n_wg) {   // [Whh_hi | Whh_hi | eW];  eW = [We_hi(4)|We_hi(4)|0]
        int np = (int)(i / KG), k = (int)(i % KG);
        int r = (np & 3) * HID + (np >> 2);
        float w = 0.f;
        if (k < 1024)        w = Whh[(size_t)r * HID + k];
        else if (k < 2048)   w = Whh[(size_t)r * HID + (k - 1024)];
        else {
            int q = k - 2048;
            if (q < 4)        w = Wih[(size_t)r * INW + CTXK + q];
            else if (q < 8)   w = Wih[(size_t)r * INW + CTXK + (q - 4)];
        }
        g_Wg[(size_t)np * KG + k] = hhi(w);
        return;
    }
    i -= n_wg;
    if (i < n_wc) {   // W_ih ctx part (3-term): [hi(512)|hi(512)|lo(512)]
        int np = (int)(i / KC), k = (int)(i % KC);
        int r = (np & 3) * HID + (np >> 2);
        int src = (k < 512) ? k : (k < 1024 ? k - 512 : k - 1024);
        float w = Wih[(size_t)r * INW + src];
        g_Wc4[(size_t)np * KC + k] = (k < 1024) ? hhi(w) : hlo(w);
        return;
    }
    i -= n_wc;
    if (i < N4) {
        int r = ((int)i & 3) * HID + ((int)i >> 2);
        g_bsum[i] = b_ih[r] + b_hh[r];
        return;
    }
    i -= N4;
    if (i < n_s) {    // Wh (3-term): [hi|hi|lo]
        int r = (int)(i / CTXK), k = (int)(i % CTXK);
        float w = Wh[(size_t)r * CTXK + k];
        size_t b = (size_t)r * KC;
        g_Whh[b + k] = hhi(w); g_Whh[b + 512 + k] = hhi(w); g_Whh[b + 1024 + k] = hlo(w);
        return;
    }
    i -= n_s;
    if (i < n_s) {    // Wc (3-term)
        int r = (int)(i / CTXK), k = (int)(i % CTXK);
        float w = Wc[(size_t)r * CTXK + k];
        size_t b = (size_t)r * KC;
        g_Wcc[b + k] = hhi(w); g_Wcc[b + 512 + k] = hhi(w); g_Wcc[b + 1024 + k] = hlo(w);
        return;
    }
    i -= n_s;
    if (i < n_w1) {   // W1 (single-term fp16)
        int r = (int)(i / HID), k = (int)(i % HID);
        g_W1s[(size_t)r * KF + k] = hhi(W1[(size_t)r * HID + k]);
    }
}

__global__ void prep_data(const float* __restrict__ ctx,
                          const float* __restrict__ last_pos,
                          const float* __restrict__ last_delta) {
    const long n_cs = (long)BATCH * CTXK;
    long i = (long)blockIdx.x * blockDim.x + threadIdx.x;
    if (i < n_cs) {
        int b = (int)(i / CTXK), k = (int)(i % CTXK);
        float v = ctx[i];
        g_ctxs[(size_t)b * ACLD + k]       = hhi(v);
        g_ctxs[(size_t)b * ACLD + 512 + k] = hlo(v);
        return;
    }
    i -= n_cs;
    if (i < BATCH) {
        int b = (int)i;
        g_pos[b * 2 + 0] = last_pos[b * 2 + 0];
        g_pos[b * 2 + 1] = last_pos[b * 2 + 1];
        float d0 = last_delta[b * 2 + 0], d1 = last_delta[b * 2 + 1];
        float nn = fmaxf(sqrtf(d0 * d0 + d1 * d1), 1e-6f);
        float e[4] = {d0, d1, d0 / nn, d1 / nn};
        size_t base = (size_t)b * AGLD;
#pragma unroll
        for (int q = 0; q < 4; q++) {
            g_Ag0[base + EBLK + q]     = hhi(e[q]);
            g_Ag0[base + EBLK + 4 + q] = hlo(e[q]);
        }
        __half z = __float2half(0.f);
        for (int k = EBLK + 8; k < AGLD; k++) { g_Ag0[base + k] = z; g_Ag1[base + k] = z; }
    }
}

// ------------------------- GEMM engine (R6/R8-proven 128x128) -------------------------
// 128x128 CTA tile, KTILE=64, 3-slot ring / 2 tiles in flight, ldmatrix,
// one __syncthreads per K-tile. 256 threads, warp grid 2Mx4N, warp tile 64x32.
#define TK 64
#define NSTG 3
#define STG_BYTES 32768          // A 16KB + B 16KB
#define GEMM_SMEM (NSTG * STG_BYTES)

enum { EPI_CTX = 0, EPI_TANH_SPLIT = 1, EPI_TANH_C = 2, EPI_GATES = 3, EPI_GELU = 4 };

__device__ __forceinline__ void lstm_cell(float* cbuf, __half* outs, int row, int j,
                                          float gi, float gf, float gg, float go) {
    float cold = cbuf[(size_t)row * HID + j];
    float si = 1.f / (1.f + expf(-gi));
    float sf = 1.f / (1.f + expf(-gf));
    float so = 1.f / (1.f + expf(-go));
    float tg = tanhf(gg);
    float cn = sf * cold + si * tg;
    float h  = so * tanhf(cn);
    cbuf[(size_t)row * HID + j] = cn;
    outs[(size_t)row * AGLD + j]        = hhi(h);
    outs[(size_t)row * AGLD + 1024 + j] = hlo(h);
}

template <int EPI>
__global__ void __launch_bounds__(256, 2)
gemm2(const __half* __restrict__ A, int lda,
      const __half* __restrict__ W, int ktot,
      int s1, int d1,                        // K->A col mapping (per 64-tile)
      const float* __restrict__ aux,
      float* __restrict__ outf,
      __half* __restrict__ outs,
      int nOut) {
    extern __shared__ __align__(1024) char smp[];
    const uint32_t sbase = (uint32_t)__cvta_generic_to_shared(smp);

    const int tid = threadIdx.x;
    const int lane = tid & 31, wid = tid >> 5;
    const int wm = wid >> 2, wn = wid & 3;
    const int m0 = blockIdx.y * 128, n0 = blockIdx.x * 128;
    const int nK = ktot / TK;

    float acc[4][4][4];
#pragma unroll
    for (int a = 0; a < 4; a++)
#pragma unroll
        for (int b = 0; b < 4; b++)
#pragma unroll
            for (int c = 0; c < 4; c++) acc[a][b][c] = 0.f;

    auto fill = [&](int kt) {
        int slot = kt % NSTG;
        uint32_t sA = sbase + slot * STG_BYTES;
        uint32_t sB = sA + 16384;
        int k0 = kt * TK;
        int cb = (k0 < s1) ? k0 : k0 - d1;
#pragma unroll
        for (int t = 0; t < 4; t++) {
            int c = tid + t * 256;
            int row = c >> 3, ch = c & 7;
            cpasync16(sA + SW128(row * 128 + ch * 16),
                      A + (size_t)(m0 + row) * lda + cb + ch * 8);
        }
#pragma unroll
        for (int t = 0; t < 4; t++) {
            int c = tid + t * 256;
            int row = c >> 3, ch = c & 7;
            cpasync16(sB + SW128(row * 128 + ch * 16),
                      W + (size_t)(n0 + row) * ktot + k0 + ch * 8);
        }
        asm volatile("cp.async.commit_group;\n");
    };

    // prologue: 2 tiles in flight
    fill(0);
    if (nK > 1) fill(1);

    const int g  = lane >> 3;
    const int lr = lane & 7;

    for (int kt = 0; kt < nK; kt++) {
        if (kt + 1 < nK) asm volatile("cp.async.wait_group 1;\n");
        else             asm volatile("cp.async.wait_group 0;\n");
        __syncthreads();                       // all warps done reading slot (kt-1)%3
        if (kt + 2 < nK) fill(kt + 2);         // safe: overwrites slot (kt-1)%3

        int slot = kt % NSTG;
        uint32_t sA = sbase + slot * STG_BYTES;
        uint32_t sB = sA + 16384;

#pragma unroll
        for (int ks = 0; ks < 4; ks++) {
            uint32_t a[4][4], b[2][4];
#pragma unroll
            for (int mf = 0; mf < 4; mf++) {
                int row = wm * 64 + mf * 16 + lr + ((g & 1) << 3);
                ldsm4(a[mf], sA + SW128(row * 128 + ks * 32 + ((g >> 1) << 4)));
            }
#pragma unroll
            for (int nf = 0; nf < 2; nf++) {
                int row = wn * 32 + nf * 16 + lr + ((g >> 1) << 3);
                ldsm4(b[nf], sB + SW128(row * 128 + ks * 32 + ((g & 1) << 4)));
            }
#pragma unroll
            for (int mf = 0; mf < 4; mf++) {
#pragma unroll
                for (int nf = 0; nf < 2; nf++) {
                    mma16816(acc[mf][2 * nf],     a[mf], &b[nf][0]);
                    mma16816(acc[mf][2 * nf + 1], a[mf], &b[nf][2]);
                }
            }
        }
    }

    // ------------------------- epilogue -------------------------
#pragma unroll
    for (int mt = 0; mt < 4; mt++) {
#pragma unroll
        for (int nt = 0; nt < 4; nt++) {
            int r = m0 + wm * 64 + mt * 16 + (lane >> 2);
            int n = n0 + wn * 32 + nt * 8 + (lane & 3) * 2;
            float v0 = acc[mt][nt][0], v1 = acc[mt][nt][1];
            float v2 = acc[mt][nt][2], v3 = acc[mt][nt][3];

            if (EPI == EPI_CTX) {
                outf[(size_t)r * nOut + n]           = v0 + aux[n];
                outf[(size_t)r * nOut + n + 1]       = v1 + aux[n + 1];
                outf[(size_t)(r + 8) * nOut + n]     = v2 + aux[n];
                outf[(size_t)(r + 8) * nOut + n + 1] = v3 + aux[n + 1];
            } else if (EPI == EPI_TANH_C) {
                outf[(size_t)r * nOut + n]           = tanhf(v0 + aux[n]);
                outf[(size_t)r * nOut + n + 1]       = tanhf(v1 + aux[n + 1]);
                outf[(size_t)(r + 8) * nOut + n]     = tanhf(v2 + aux[n]);
                outf[(size_t)(r + 8) * nOut + n + 1] = tanhf(v3 + aux[n + 1]);
            } else if (EPI == EPI_TANH_SPLIT) {
#pragma unroll
                for (int q = 0; q < 4; q++) {
                    int rr = (q >= 2) ? r + 8 : r;
                    int nn = n + (q & 1);
                    float v = (q == 0) ? v0 : (q == 1) ? v1 : (q == 2) ? v2 : v3;
                    float h = tanhf(v + aux[nn]);
                    outs[(size_t)rr * AGLD + nn]        = hhi(h);
                    outs[(size_t)rr * AGLD + 1024 + nn] = hlo(h);
                }
            } else if (EPI == EPI_GELU) {
#pragma unroll
                for (int q = 0; q < 4; q++) {
                    int rr = (q >= 2) ? r + 8 : r;
                    int nn = n + (q & 1);
                    float v = (q == 0) ? v0 : (q == 1) ? v1 : (q == 2) ? v2 : v3;
                    float u = v + aux[nn];
                    outf[(size_t)rr * nOut + nn] = 0.5f * u * (1.f + erff(u * 0.70710678118654752f));
                }
            } else { // EPI_GATES
                float w0 = v0 + aux[(size_t)r * N4 + n];
                float w1 = v1 + aux[(size_t)r * N4 + n + 1];
                float w2 = v2 + aux[(size_t)(r + 8) * N4 + n];
                float w3 = v3 + aux[(size_t)(r + 8) * N4 + n + 1];
                float u0 = __shfl_xor_sync(0xffffffffu, w0, 1);
                float u1 = __shfl_xor_sync(0xffffffffu, w1, 1);
                float u2 = __shfl_xor_sync(0xffffffffu, w2, 1);
                float u3 = __shfl_xor_sync(0xffffffffu, w3, 1);
                if (!(lane & 1)) {   // even lanes own (i,f); lane^1 holds (g,o)
                    int j = n >> 2;
                    lstm_cell(outf, outs, r, j, w0, w1, u0, u1);
                    lstm_cell(outf, outs, r + 8, j, w2, w3, u2, u3);
                }
            }
        }
    }
}

// ------------------------- LayerNorm (warp per row) -------------------------
__global__ void ln_kernel(const __half* __restrict__ Ag,
                          const float* __restrict__ gam, const float* __restrict__ bet) {
    int warp = (blockIdx.x * blockDim.x + threadIdx.x) >> 5;
    int lane = threadIdx.x & 31;
    if (warp >= BATCH) return;
    size_t base = (size_t)warp * AGLD;
    float h[32];
    float s = 0.f, ss = 0.f;
#pragma unroll
    for (int i = 0; i < 32; i++) {
        int k = lane + 32 * i;
        float v = __half2float(Ag[base + k]) + __half2float(Ag[base + 1024 + k]);
        h[i] = v; s += v; ss += v * v;
    }
#pragma unroll
    for (int o = 16; o; o >>= 1) {
        s  += __shfl_xor_sync(0xffffffffu, s, o);
        ss += __shfl_xor_sync(0xffffffffu, ss, o);
    }
    float mu = s * (1.f / HID);
    float var = ss * (1.f / HID) - mu * mu;
    float inv = rsqrtf(var + 1e-5f);
    size_t ob = (size_t)warp * AFLD;
#pragma unroll
    for (int i = 0; i < 32; i++) {
        int k = lane + 32 * i;
        float y = (h[i] - mu) * inv * gam[k] + bet[k];
        g_Af[ob + k] = hhi(y);
    }
}

// ------------------------- delta / pos head (warp per row) -------------------------
__global__ void delta_kernel(const float* __restrict__ W2, const float* __restrict__ b2,
                             float* __restrict__ out, int t, __half* __restrict__ AgN) {
    int warp = (blockIdx.x * blockDim.x + threadIdx.x) >> 5;
    int lane = threadIdx.x & 31;
    if (warp >= BATCH) return;
    const float* y = g_y2 + (size_t)warp * HID;
    float a0 = 0.f, a1 = 0.f;
#pragma unroll
    for (int i = 0; i < 32; i++) {
        int k = lane + 32 * i;
        float v = y[k];
        a0 += v * W2[k];
        a1 += v * W2[HID + k];
    }
#pragma unroll
    for (int o = 16; o; o >>= 1) {
        a0 += __shfl_xor_sync(0xffffffffu, a0, o);
        a1 += __shfl_xor_sync(0xffffffffu, a1, o);
    }
    if (lane == 0) {
        float d0 = a0 + b2[0], d1 = a1 + b2[1];
        float p0 = g_pos[warp * 2 + 0] + d0;
        float p1 = g_pos[warp * 2 + 1] + d1;
        g_pos[warp * 2 + 0] = p0;
        g_pos[warp * 2 + 1] = p1;
        out[(size_t)warp * (TSTEPS * 2) + t * 2 + 0] = p0;
        out[(size_t)warp * (TSTEPS * 2) + t * 2 + 1] = p1;
        float nn = fmaxf(sqrtf(d0 * d0 + d1 * d1), 1e-6f);
        float e[4] = {d0, d1, d0 / nn, d1 / nn};
        size_t base = (size_t)warp * AGLD;
#pragma unroll
        for (int q = 0; q < 4; q++) {
            AgN[base + EBLK + q]     = hhi(e[q]);
            AgN[base + EBLK + 4 + q] = hlo(e[q]);
        }
    }
}

// ------------------------- host -------------------------
static inline int nb(long n) { return (int)((n + 255) / 256); }

extern "C" void kernel_launch(void* const* d_in, const int* in_sizes, int n_in,
                              void* d_out, int out_size) {
    const float* context    = (const float*)d_in[0];
    const float* last_pos   = (const float*)d_in[1];
    const float* last_delta = (const float*)d_in[2];
    const float* Wh   = (const float*)d_in[3];
    const float* bh   = (const float*)d_in[4];
    const float* Wc   = (const float*)d_in[5];
    const float* bc   = (const float*)d_in[6];
    const float* W_ih = (const float*)d_in[7];
    const float* b_ih = (const float*)d_in[8];
    const float* W_hh = (const float*)d_in[9];
    const float* b_hh = (const float*)d_in[10];
    const float* ln_g = (const float*)d_in[11];
    const float* ln_b = (const float*)d_in[12];
    const float* W1   = (const float*)d_in[13];
    const float* b1   = (const float*)d_in[14];
    const float* W2   = (const float*)d_in[15];
    const float* b2   = (const float*)d_in[16];
    float* out = (float*)d_out;

    __half *pCtxs, *pAg0, *pAg1, *pAf, *pWg, *pWc4, *pWhh, *pWcc, *pW1s;
    float *pGctx, *pC, *pY2, *pBsum;
    cudaGetSymbolAddress((void**)&pCtxs, g_ctxs);
    cudaGetSymbolAddress((void**)&pAg0, g_Ag0);
    cudaGetSymbolAddress((void**)&pAg1, g_Ag1);
    cudaGetSymbolAddress((void**)&pAf,  g_Af);
    cudaGetSymbolAddress((void**)&pWg,  g_Wg);
    cudaGetSymbolAddress((void**)&pWc4, g_Wc4);
    cudaGetSymbolAddress((void**)&pWhh, g_Whh);
    cudaGetSymbolAddress((void**)&pWcc, g_Wcc);
    cudaGetSymbolAddress((void**)&pW1s, g_W1s);
    cudaGetSymbolAddress((void**)&pGctx, g_gctx);
    cudaGetSymbolAddress((void**)&pC,   g_c);
    cudaGetSymbolAddress((void**)&pY2,  g_y2);
    cudaGetSymbolAddress((void**)&pBsum, g_bsum);

    cudaFuncSetAttribute(gemm2<EPI_CTX>,        cudaFuncAttributeMaxDynamicSharedMemorySize, GEMM_SMEM);
    cudaFuncSetAttribute(gemm2<EPI_TANH_SPLIT>, cudaFuncAttributeMaxDynamicSharedMemorySize, GEMM_SMEM);
    cudaFuncSetAttribute(gemm2<EPI_TANH_C>,     cudaFuncAttributeMaxDynamicSharedMemorySize, GEMM_SMEM);
    cudaFuncSetAttribute(gemm2<EPI_GATES>,      cudaFuncAttributeMaxDynamicSharedMemorySize, GEMM_SMEM);
    cudaFuncSetAttribute(gemm2<EPI_GELU>,       cudaFuncAttributeMaxDynamicSharedMemorySize, GEMM_SMEM);

    const int BIG = 1 << 30;

    {
        long tot = (long)N4 * KG + (long)N4 * KC + N4
                 + (long)HID * CTXK * 2 + (long)HID * HID;
        prep_weights<<<nb(tot), 256>>>(W_hh, W_ih, b_ih, b_hh, Wh, Wc, W1);
    }
    {
        long tot = (long)BATCH * CTXK + BATCH;
        prep_data<<<nb(tot), 256>>>(context, last_pos, last_delta);
    }

    dim3 blk(256);
    dim3 grid_n4(N4 / 128, BATCH / 128);   // (32,128)
    dim3 grid_h(HID / 128, BATCH / 128);   // (8,128)

    // gates_ctx (3-term), hidden/cell init (3-term)
    gemm2<EPI_CTX><<<grid_n4, blk, GEMM_SMEM>>>(pCtxs, ACLD, pWc4, KC, 1024, 1024,
                                                pBsum, pGctx, nullptr, N4);
    gemm2<EPI_TANH_SPLIT><<<grid_h, blk, GEMM_SMEM>>>(pCtxs, ACLD, pWhh, KC, 1024, 1024,
                                                      bh, nullptr, pAg0, HID);
    gemm2<EPI_TANH_C><<<grid_h, blk, GEMM_SMEM>>>(pCtxs, ACLD, pWcc, KC, 1024, 1024,
                                                  bc, pC, nullptr, HID);

    __half* Ag[2] = {pAg0, pAg1};
    for (int t = 0; t < TSTEPS; t++) {
        int cur = t & 1, nxt = cur ^ 1;
        gemm2<EPI_GATES><<<grid_n4, blk, GEMM_SMEM>>>(Ag[cur], AGLD, pWg, KG, BIG, 0,
                                                      pGctx, pC, Ag[nxt], N4);
        ln_kernel<<<BATCH / 8, 256>>>(Ag[nxt], ln_g, ln_b);
        gemm2<EPI_GELU><<<grid_h, blk, GEMM_SMEM>>>(pAf, AFLD, pW1s, KF, BIG, 0,
                                                    b1, pY2, nullptr, HID);
        delta_kernel<<<BATCH / 8, 256>>>(W2, b2, out, t, Ag[nxt]);
    }
}

// round 11
// speedup vs baseline: 2.1059x; 1.0169x over previous
#include <cuda_runtime.h>
#include <cuda_fp16.h>
#include <math.h>
#include <stdint.h>

#define BATCH   16384
#define HID     1024
#define CTXK    512
#define N4      4096
#define TSTEPS  60
#define INW     516     // W_ih row width (C+4)

// fp16 2-term split for gates GEMM: x*W ~= (x_hi + x_lo) * W_hi
// gates GEMM: A row = K row = [h_hi(1024) | h_lo(1024) | eblk(64)] -> KG=2112=33*64
//   eblk = [e_hi(4) | e_lo(4) | zeros(56)]
#define AGLD    2112
#define EBLK    2048
#define KG      2112
// ffn GEMM (single-term fp16, non-recurrent path): A row = K row = [y(1024)]
#define AFLD    1024
#define KF      1024
// context GEMMs (one-time, 3-term fp16): A row = [c_hi(512)|c_lo(512)];
//   K = [c_hi | c_lo | c_hi(re-read)] = 1536 ; W = [W_hi|W_hi|W_lo]
#define ACLD    1024
#define KC      1536

// ------------------------- scratch (device globals) -------------------------
__device__ __align__(256) float   g_gctx[(size_t)BATCH * N4];
__device__ __align__(256) __half  g_Ag0[(size_t)BATCH * AGLD];
__device__ __align__(256) __half  g_Ag1[(size_t)BATCH * AGLD];
__device__ __align__(256) __half  g_Af [(size_t)BATCH * AFLD];
__device__ __align__(256) __half  g_ctxs[(size_t)BATCH * ACLD];
__device__ __align__(256) float   g_c  [(size_t)BATCH * HID];
__device__ __align__(256) float   g_y2 [(size_t)BATCH * HID];
__device__ __align__(256) float   g_pos[(size_t)BATCH * 2];
__device__ __align__(256) __half  g_Wg  [(size_t)N4 * KG];
__device__ __align__(256) __half  g_Wc4 [(size_t)N4 * KC];
__device__ __align__(256) __half  g_Whh [(size_t)HID * KC];
__device__ __align__(256) __half  g_Wcc [(size_t)HID * KC];
__device__ __align__(256) __half  g_W1s [(size_t)HID * KF];
__device__ __align__(256) float   g_bsum[N4];

// ------------------------- low-level helpers -------------------------
#define SW128(b) ((b) ^ (((b) >> 3) & 0x70))

__device__ __forceinline__ void cpasync16(uint32_t dst, const void* src) {
    asm volatile("cp.async.cg.shared.global [%0],[%1],16;\n" :: "r"(dst), "l"(src));
}
__device__ __forceinline__ void ldsm4(uint32_t* r, uint32_t addr) {
    asm volatile("ldmatrix.sync.aligned.m8n8.x4.shared.b16 {%0,%1,%2,%3}, [%4];"
                 : "=r"(r[0]), "=r"(r[1]), "=r"(r[2]), "=r"(r[3]) : "r"(addr));
}
__device__ __forceinline__ void mma16816(float* c, const uint32_t* a, const uint32_t* b) {
    asm volatile(
        "mma.sync.aligned.m16n8k16.row.col.f32.f16.f16.f32 "
        "{%0,%1,%2,%3},{%4,%5,%6,%7},{%8,%9},{%0,%1,%2,%3};\n"
        : "+f"(c[0]), "+f"(c[1]), "+f"(c[2]), "+f"(c[3])
        : "r"(a[0]), "r"(a[1]), "r"(a[2]), "r"(a[3]), "r"(b[0]), "r"(b[1]));
}
__device__ __forceinline__ __half hhi(float v) { return __float2half_rn(v); }
__device__ __forceinline__ __half hlo(float v) {
    return __float2half_rn(v - __half2float(__float2half_rn(v)));
}
// fast activations: __expf (MUFU.EX2) + __fdividef (MUFU.RCP), rel err ~2^-21
__device__ __forceinline__ float fsig(float x) {
    return __fdividef(1.f, 1.f + __expf(-x));
}
__device__ __forceinline__ float ftanh(float x) {
    return 1.f - __fdividef(2.f, __expf(2.f * x) + 1.f);   // exact identity
}

// ------------------------- prep kernels -------------------------
__global__ void prep_weights(const float* __restrict__ Whh, const float* __restrict__ Wih,
                             const float* __restrict__ b_ih, const float* __restrict__ b_hh,
                             const float* __restrict__ Wh, const float* __restrict__ Wc,
                             const float* __restrict__ W1) {
    const long n_wg = (long)N4 * KG;
    const long n_wc = (long)N4 * KC;
    const long n_s  = (long)HID * CTXK;
    const long n_w1 = (long)HID * HID;
    long i = (long)blockIdx.x * blockDim.x + threadIdx.x;

    if (i < n_wg) {   // [Whh_hi | Whh_hi | eW];  eW = [We_hi(4)|We_hi(4)|0]
        int np = (int)(i / KG), k = (int)(i % KG);
        int r = (np & 3) * HID + (np >> 2);
        float w = 0.f;
        if (k < 1024)        w = Whh[(size_t)r * HID + k];
        else if (k < 2048)   w = Whh[(size_t)r * HID + (k - 1024)];
        else {
            int q = k - 2048;
            if (q < 4)        w = Wih[(size_t)r * INW + CTXK + q];
            else if (q < 8)   w = Wih[(size_t)r * INW + CTXK + (q - 4)];
        }
        g_Wg[(size_t)np * KG + k] = hhi(w);
        return;
    }
    i -= n_wg;
    if (i < n_wc) {   // W_ih ctx part (3-term): [hi(512)|hi(512)|lo(512)]
        int np = (int)(i / KC), k = (int)(i % KC);
        int r = (np & 3) * HID + (np >> 2);
        int src = (k < 512) ? k : (k < 1024 ? k - 512 : k - 1024);
        float w = Wih[(size_t)r * INW + src];
        g_Wc4[(size_t)np * KC + k] = (k < 1024) ? hhi(w) : hlo(w);
        return;
    }
    i -= n_wc;
    if (i < N4) {
        int r = ((int)i & 3) * HID + ((int)i >> 2);
        g_bsum[i] = b_ih[r] + b_hh[r];
        return;
    }
    i -= N4;
    if (i < n_s) {    // Wh (3-term): [hi|hi|lo]
        int r = (int)(i / CTXK), k = (int)(i % CTXK);
        float w = Wh[(size_t)r * CTXK + k];
        size_t b = (size_t)r * KC;
        g_Whh[b + k] = hhi(w); g_Whh[b + 512 + k] = hhi(w); g_Whh[b + 1024 + k] = hlo(w);
        return;
    }
    i -= n_s;
    if (i < n_s) {    // Wc (3-term)
        int r = (int)(i / CTXK), k = (int)(i % CTXK);
        float w = Wc[(size_t)r * CTXK + k];
        size_t b = (size_t)r * KC;
        g_Wcc[b + k] = hhi(w); g_Wcc[b + 512 + k] = hhi(w); g_Wcc[b + 1024 + k] = hlo(w);
        return;
    }
    i -= n_s;
    if (i < n_w1) {   // W1 (single-term fp16)
        int r = (int)(i / HID), k = (int)(i % HID);
        g_W1s[(size_t)r * KF + k] = hhi(W1[(size_t)r * HID + k]);
    }
}

__global__ void prep_data(const float* __restrict__ ctx,
                          const float* __restrict__ last_pos,
                          const float* __restrict__ last_delta) {
    const long n_cs = (long)BATCH * CTXK;
    long i = (long)blockIdx.x * blockDim.x + threadIdx.x;
    if (i < n_cs) {
        int b = (int)(i / CTXK), k = (int)(i % CTXK);
        float v = ctx[i];
        g_ctxs[(size_t)b * ACLD + k]       = hhi(v);
        g_ctxs[(size_t)b * ACLD + 512 + k] = hlo(v);
        return;
    }
    i -= n_cs;
    if (i < BATCH) {
        int b = (int)i;
        g_pos[b * 2 + 0] = last_pos[b * 2 + 0];
        g_pos[b * 2 + 1] = last_pos[b * 2 + 1];
        float d0 = last_delta[b * 2 + 0], d1 = last_delta[b * 2 + 1];
        float nn = fmaxf(sqrtf(d0 * d0 + d1 * d1), 1e-6f);
        float e[4] = {d0, d1, d0 / nn, d1 / nn};
        size_t base = (size_t)b * AGLD;
#pragma unroll
        for (int q = 0; q < 4; q++) {
            g_Ag0[base + EBLK + q]     = hhi(e[q]);
            g_Ag0[base + EBLK + 4 + q] = hlo(e[q]);
        }
        __half z = __float2half(0.f);
        for (int k = EBLK + 8; k < AGLD; k++) { g_Ag0[base + k] = z; g_Ag1[base + k] = z; }
    }
}

// ------------------------- GEMM engine (R6/R8-proven 128x128) -------------------------
// 128x128 CTA tile, KTILE=64, 3-slot ring / 2 tiles in flight, ldmatrix,
// one __syncthreads per K-tile. 256 threads, warp grid 2Mx4N, warp tile 64x32.
#define TK 64
#define NSTG 3
#define STG_BYTES 32768          // A 16KB + B 16KB
#define GEMM_SMEM (NSTG * STG_BYTES)

enum { EPI_CTX = 0, EPI_TANH_SPLIT = 1, EPI_TANH_C = 2, EPI_GATES = 3, EPI_GELU = 4 };

__device__ __forceinline__ void lstm_cell(float* cbuf, __half* outs, int row, int j,
                                          float gi, float gf, float gg, float go) {
    float cold = cbuf[(size_t)row * HID + j];
    float si = fsig(gi);
    float sf = fsig(gf);
    float so = fsig(go);
    float tg = ftanh(gg);
    float cn = sf * cold + si * tg;
    float h  = so * ftanh(cn);
    cbuf[(size_t)row * HID + j] = cn;
    outs[(size_t)row * AGLD + j]        = hhi(h);
    outs[(size_t)row * AGLD + 1024 + j] = hlo(h);
}

template <int EPI>
__global__ void __launch_bounds__(256, 2)
gemm2(const __half* __restrict__ A, int lda,
      const __half* __restrict__ W, int ktot,
      int s1, int d1,                        // K->A col mapping (per 64-tile)
      const float* __restrict__ aux,
      float* __restrict__ outf,
      __half* __restrict__ outs,
      int nOut) {
    extern __shared__ __align__(1024) char smp[];
    const uint32_t sbase = (uint32_t)__cvta_generic_to_shared(smp);

    const int tid = threadIdx.x;
    const int lane = tid & 31, wid = tid >> 5;
    const int wm = wid >> 2, wn = wid & 3;
    const int m0 = blockIdx.y * 128, n0 = blockIdx.x * 128;
    const int nK = ktot / TK;

    float acc[4][4][4];
#pragma unroll
    for (int a = 0; a < 4; a++)
#pragma unroll
        for (int b = 0; b < 4; b++)
#pragma unroll
            for (int c = 0; c < 4; c++) acc[a][b][c] = 0.f;

    auto fill = [&](int kt) {
        int slot = kt % NSTG;
        uint32_t sA = sbase + slot * STG_BYTES;
        uint32_t sB = sA + 16384;
        int k0 = kt * TK;
        int cb = (k0 < s1) ? k0 : k0 - d1;
#pragma unroll
        for (int t = 0; t < 4; t++) {
            int c = tid + t * 256;
            int row = c >> 3, ch = c & 7;
            cpasync16(sA + SW128(row * 128 + ch * 16),
                      A + (size_t)(m0 + row) * lda + cb + ch * 8);
        }
#pragma unroll
        for (int t = 0; t < 4; t++) {
            int c = tid + t * 256;
            int row = c >> 3, ch = c & 7;
            cpasync16(sB + SW128(row * 128 + ch * 16),
                      W + (size_t)(n0 + row) * ktot + k0 + ch * 8);
        }
        asm volatile("cp.async.commit_group;\n");
    };

    // prologue: 2 tiles in flight
    fill(0);
    if (nK > 1) fill(1);

    const int g  = lane >> 3;
    const int lr = lane & 7;

    for (int kt = 0; kt < nK; kt++) {
        if (kt + 1 < nK) asm volatile("cp.async.wait_group 1;\n");
        else             asm volatile("cp.async.wait_group 0;\n");
        __syncthreads();                       // all warps done reading slot (kt-1)%3
        if (kt + 2 < nK) fill(kt + 2);         // safe: overwrites slot (kt-1)%3

        int slot = kt % NSTG;
        uint32_t sA = sbase + slot * STG_BYTES;
        uint32_t sB = sA + 16384;

#pragma unroll
        for (int ks = 0; ks < 4; ks++) {
            uint32_t a[4][4], b[2][4];
#pragma unroll
            for (int mf = 0; mf < 4; mf++) {
                int row = wm * 64 + mf * 16 + lr + ((g & 1) << 3);
                ldsm4(a[mf], sA + SW128(row * 128 + ks * 32 + ((g >> 1) << 4)));
            }
#pragma unroll
            for (int nf = 0; nf < 2; nf++) {
                int row = wn * 32 + nf * 16 + lr + ((g >> 1) << 3);
                ldsm4(b[nf], sB + SW128(row * 128 + ks * 32 + ((g & 1) << 4)));
            }
#pragma unroll
            for (int mf = 0; mf < 4; mf++) {
#pragma unroll
                for (int nf = 0; nf < 2; nf++) {
                    mma16816(acc[mf][2 * nf],     a[mf], &b[nf][0]);
                    mma16816(acc[mf][2 * nf + 1], a[mf], &b[nf][2]);
                }
            }
        }
    }

    // ------------------------- epilogue -------------------------
#pragma unroll
    for (int mt = 0; mt < 4; mt++) {
#pragma unroll
        for (int nt = 0; nt < 4; nt++) {
            int r = m0 + wm * 64 + mt * 16 + (lane >> 2);
            int n = n0 + wn * 32 + nt * 8 + (lane & 3) * 2;
            float v0 = acc[mt][nt][0], v1 = acc[mt][nt][1];
            float v2 = acc[mt][nt][2], v3 = acc[mt][nt][3];

            if (EPI == EPI_CTX) {
                outf[(size_t)r * nOut + n]           = v0 + aux[n];
                outf[(size_t)r * nOut + n + 1]       = v1 + aux[n + 1];
                outf[(size_t)(r + 8) * nOut + n]     = v2 + aux[n];
                outf[(size_t)(r + 8) * nOut + n + 1] = v3 + aux[n + 1];
            } else if (EPI == EPI_TANH_C) {
                outf[(size_t)r * nOut + n]           = ftanh(v0 + aux[n]);
                outf[(size_t)r * nOut + n + 1]       = ftanh(v1 + aux[n + 1]);
                outf[(size_t)(r + 8) * nOut + n]     = ftanh(v2 + aux[n]);
                outf[(size_t)(r + 8) * nOut + n + 1] = ftanh(v3 + aux[n + 1]);
            } else if (EPI == EPI_TANH_SPLIT) {
#pragma unroll
                for (int q = 0; q < 4; q++) {
                    int rr = (q >= 2) ? r + 8 : r;
                    int nn = n + (q & 1);
                    float v = (q == 0) ? v0 : (q == 1) ? v1 : (q == 2) ? v2 : v3;
                    float h = ftanh(v + aux[nn]);
                    outs[(size_t)rr * AGLD + nn]        = hhi(h);
                    outs[(size_t)rr * AGLD + 1024 + nn] = hlo(h);
                }
            } else if (EPI == EPI_GELU) {
#pragma unroll
                for (int q = 0; q < 4; q++) {
                    int rr = (q >= 2) ? r + 8 : r;
                    int nn = n + (q & 1);
                    float v = (q == 0) ? v0 : (q == 1) ? v1 : (q == 2) ? v2 : v3;
                    float u = v + aux[nn];
                    outf[(size_t)rr * nOut + nn] = 0.5f * u * (1.f + erff(u * 0.70710678118654752f));
                }
            } else { // EPI_GATES
                float w0 = v0 + aux[(size_t)r * N4 + n];
                float w1 = v1 + aux[(size_t)r * N4 + n + 1];
                float w2 = v2 + aux[(size_t)(r + 8) * N4 + n];
                float w3 = v3 + aux[(size_t)(r + 8) * N4 + n + 1];
                float u0 = __shfl_xor_sync(0xffffffffu, w0, 1);
                float u1 = __shfl_xor_sync(0xffffffffu, w1, 1);
                float u2 = __shfl_xor_sync(0xffffffffu, w2, 1);
                float u3 = __shfl_xor_sync(0xffffffffu, w3, 1);
                if (!(lane & 1)) {   // even lanes own (i,f); lane^1 holds (g,o)
                    int j = n >> 2;
                    lstm_cell(outf, outs, r, j, w0, w1, u0, u1);
                    lstm_cell(outf, outs, r + 8, j, w2, w3, u2, u3);
                }
            }
        }
    }
}

// ------------------------- LayerNorm (warp per row) -------------------------
__global__ void ln_kernel(const __half* __restrict__ Ag,
                          const float* __restrict__ gam, const float* __restrict__ bet) {
    int warp = (blockIdx.x * blockDim.x + threadIdx.x) >> 5;
    int lane = threadIdx.x & 31;
    if (warp >= BATCH) return;
    size_t base = (size_t)warp * AGLD;
    float h[32];
    float s = 0.f, ss = 0.f;
#pragma unroll
    for (int i = 0; i < 32; i++) {
        int k = lane + 32 * i;
        float v = __half2float(Ag[base + k]) + __half2float(Ag[base + 1024 + k]);
        h[i] = v; s += v; ss += v * v;
    }
#pragma unroll
    for (int o = 16; o; o >>= 1) {
        s  += __shfl_xor_sync(0xffffffffu, s, o);
        ss += __shfl_xor_sync(0xffffffffu, ss, o);
    }
    float mu = s * (1.f / HID);
    float var = ss * (1.f / HID) - mu * mu;
    float inv = rsqrtf(var + 1e-5f);
    size_t ob = (size_t)warp * AFLD;
#pragma unroll
    for (int i = 0; i < 32; i++) {
        int k = lane + 32 * i;
        float y = (h[i] - mu) * inv * gam[k] + bet[k];
        g_Af[ob + k] = hhi(y);
    }
}

// ------------------------- delta / pos head (warp per row) -------------------------
__global__ void delta_kernel(const float* __restrict__ W2, const float* __restrict__ b2,
                             float* __restrict__ out, int t, __half* __restrict__ AgN) {
    int warp = (blockIdx.x * blockDim.x + threadIdx.x) >> 5;
    int lane = threadIdx.x & 31;
    if (warp >= BATCH) return;
    const float* y = g_y2 + (size_t)warp * HID;
    float a0 = 0.f, a1 = 0.f;
#pragma unroll
    for (int i = 0; i < 32; i++) {
        int k = lane + 32 * i;
        float v = y[k];
        a0 += v * W2[k];
        a1 += v * W2[HID + k];
    }
#pragma unroll
    for (int o = 16; o; o >>= 1) {
        a0 += __shfl_xor_sync(0xffffffffu, a0, o);
        a1 += __shfl_xor_sync(0xffffffffu, a1, o);
    }
    if (lane == 0) {
        float d0 = a0 + b2[0], d1 = a1 + b2[1];
        float p0 = g_pos[warp * 2 + 0] + d0;
        float p1 = g_pos[warp * 2 + 1] + d1;
        g_pos[warp * 2 + 0] = p0;
        g_pos[warp * 2 + 1] = p1;
        out[(size_t)warp * (TSTEPS * 2) + t * 2 + 0] = p0;
        out[(size_t)warp * (TSTEPS * 2) + t * 2 + 1] = p1;
        float nn = fmaxf(sqrtf(d0 * d0 + d1 * d1), 1e-6f);
        float e[4] = {d0, d1, d0 / nn, d1 / nn};
        size_t base = (size_t)warp * AGLD;
#pragma unroll
        for (int q = 0; q < 4; q++) {
            AgN[base + EBLK + q]     = hhi(e[q]);
            AgN[base + EBLK + 4 + q] = hlo(e[q]);
        }
    }
}

// ------------------------- host -------------------------
static inline int nb(long n) { return (int)((n + 255) / 256); }

extern "C" void kernel_launch(void* const* d_in, const int* in_sizes, int n_in,
                              void* d_out, int out_size) {
    const float* context    = (const float*)d_in[0];
    const float* last_pos   = (const float*)d_in[1];
    const float* last_delta = (const float*)d_in[2];
    const float* Wh   = (const float*)d_in[3];
    const float* bh   = (const float*)d_in[4];
    const float* Wc   = (const float*)d_in[5];
    const float* bc   = (const float*)d_in[6];
    const float* W_ih = (const float*)d_in[7];
    const float* b_ih = (const float*)d_in[8];
    const float* W_hh = (const float*)d_in[9];
    const float* b_hh = (const float*)d_in[10];
    const float* ln_g = (const float*)d_in[11];
    const float* ln_b = (const float*)d_in[12];
    const float* W1   = (const float*)d_in[13];
    const float* b1   = (const float*)d_in[14];
    const float* W2   = (const float*)d_in[15];
    const float* b2   = (const float*)d_in[16];
    float* out = (float*)d_out;

    __half *pCtxs, *pAg0, *pAg1, *pAf, *pWg, *pWc4, *pWhh, *pWcc, *pW1s;
    float *pGctx, *pC, *pY2, *pBsum;
    cudaGetSymbolAddress((void**)&pCtxs, g_ctxs);
    cudaGetSymbolAddress((void**)&pAg0, g_Ag0);
    cudaGetSymbolAddress((void**)&pAg1, g_Ag1);
    cudaGetSymbolAddress((void**)&pAf,  g_Af);
    cudaGetSymbolAddress((void**)&pWg,  g_Wg);
    cudaGetSymbolAddress((void**)&pWc4, g_Wc4);
    cudaGetSymbolAddress((void**)&pWhh, g_Whh);
    cudaGetSymbolAddress((void**)&pWcc, g_Wcc);
    cudaGetSymbolAddress((void**)&pW1s, g_W1s);
    cudaGetSymbolAddress((void**)&pGctx, g_gctx);
    cudaGetSymbolAddress((void**)&pC,   g_c);
    cudaGetSymbolAddress((void**)&pY2,  g_y2);
    cudaGetSymbolAddress((void**)&pBsum, g_bsum);

    cudaFuncSetAttribute(gemm2<EPI_CTX>,        cudaFuncAttributeMaxDynamicSharedMemorySize, GEMM_SMEM);
    cudaFuncSetAttribute(gemm2<EPI_TANH_SPLIT>, cudaFuncAttributeMaxDynamicSharedMemorySize, GEMM_SMEM);
    cudaFuncSetAttribute(gemm2<EPI_TANH_C>,     cudaFuncAttributeMaxDynamicSharedMemorySize, GEMM_SMEM);
    cudaFuncSetAttribute(gemm2<EPI_GATES>,      cudaFuncAttributeMaxDynamicSharedMemorySize, GEMM_SMEM);
    cudaFuncSetAttribute(gemm2<EPI_GELU>,       cudaFuncAttributeMaxDynamicSharedMemorySize, GEMM_SMEM);

    const int BIG = 1 << 30;

    {
        long tot = (long)N4 * KG + (long)N4 * KC + N4
                 + (long)HID * CTXK * 2 + (long)HID * HID;
        prep_weights<<<nb(tot), 256>>>(W_hh, W_ih, b_ih, b_hh, Wh, Wc, W1);
    }
    {
        long tot = (long)BATCH * CTXK + BATCH;
        prep_data<<<nb(tot), 256>>>(context, last_pos, last_delta);
    }

    dim3 blk(256);
    dim3 grid_n4(N4 / 128, BATCH / 128);   // (32,128)
    dim3 grid_h(HID / 128, BATCH / 128);   // (8,128)

    // gates_ctx (3-term), hidden/cell init (3-term)
    gemm2<EPI_CTX><<<grid_n4, blk, GEMM_SMEM>>>(pCtxs, ACLD, pWc4, KC, 1024, 1024,
                                                pBsum, pGctx, nullptr, N4);
    gemm2<EPI_TANH_SPLIT><<<grid_h, blk, GEMM_SMEM>>>(pCtxs, ACLD, pWhh, KC, 1024, 1024,
                                                      bh, nullptr, pAg0, HID);
    gemm2<EPI_TANH_C><<<grid_h, blk, GEMM_SMEM>>>(pCtxs, ACLD, pWcc, KC, 1024, 1024,
                                                  bc, pC, nullptr, HID);

    __half* Ag[2] = {pAg0, pAg1};
    for (int t = 0; t < TSTEPS; t++) {
        int cur = t & 1, nxt = cur ^ 1;
        gemm2<EPI_GATES><<<grid_n4, blk, GEMM_SMEM>>>(Ag[cur], AGLD, pWg, KG, BIG, 0,
                                                      pGctx, pC, Ag[nxt], N4);
        ln_kernel<<<BATCH / 8, 256>>>(Ag[nxt], ln_g, ln_b);
        gemm2<EPI_GELU><<<grid_h, blk, GEMM_SMEM>>>(pAf, AFLD, pW1s, KF, BIG, 0,
                                                    b1, pY2, nullptr, HID);
        delta_kernel<<<BATCH / 8, 256>>>(W2, b2, out, t, Ag[nxt]);
    }
}